// round 4
// baseline (speedup 1.0000x reference)
#include <cuda_runtime.h>
#include <math.h>

#define BATCH 4
#define CH    256
#define NSP   4096
#define DQK   32

// ---------------- scratch (__device__ globals: no runtime allocation) -------
__device__ __align__(256) float g_Q[BATCH*NSP*DQK];   // [b][n][d]
__device__ __align__(256) float g_K[BATCH*NSP*DQK];   // [b][n][d]
__device__ __align__(256) float g_V[BATCH*NSP*CH];    // [b][n][e]
__device__ __align__(256) float g_G0[CH*CH];
__device__ __align__(256) float g_GA[CH*CH];
__device__ __align__(256) float g_GB[CH*CH];
__device__ float g_tr[16];
__device__ float g_sigma[4];   // [0]=sigma_q [1]=sigma_k [2]=sigma_v

// ---------------- packed f32x2 helpers (Blackwell) --------------------------
__device__ __forceinline__ unsigned long long pk2(float lo, float hi){
    unsigned long long r;
    asm("mov.b64 %0, {%1, %2};" : "=l"(r) : "f"(lo), "f"(hi));
    return r;
}
__device__ __forceinline__ void upk2(unsigned long long a, float& lo, float& hi){
    asm("mov.b64 {%0, %1}, %2;" : "=f"(lo), "=f"(hi) : "l"(a));
}
__device__ __forceinline__ unsigned long long ffma2(unsigned long long a,
                                                    unsigned long long b,
                                                    unsigned long long c){
    unsigned long long d;
    asm("fma.rn.f32x2 %0, %1, %2, %3;" : "=l"(d) : "l"(a), "l"(b), "l"(c));
    return d;
}
__device__ __forceinline__ unsigned long long fmul2(unsigned long long a,
                                                    unsigned long long b){
    unsigned long long d;
    asm("mul.rn.f32x2 %0, %1, %2;" : "=l"(d) : "l"(a), "l"(b));
    return d;
}

// ---------------- init ------------------------------------------------------
__global__ void init_kernel(){
    if (threadIdx.x < 16) g_tr[threadIdx.x] = 0.0f;
}

// ---------------- sigma for wq / wk (32x256) --------------------------------
// A = W W^T (32x32); 5 trace-normalized in-smem squarings -> ~A^32;
// 40 power steps; Rayleigh quotient against original A. Effective power ~1280.
__global__ void sigma_qk_kernel(const float* __restrict__ wq,
                                const float* __restrict__ wk){
    const float* W = (blockIdx.x == 0) ? wq : wk;
    __shared__ float Ws[32][257];
    __shared__ float Ao[32][33];
    __shared__ float Aa[32][33];
    __shared__ float Ab[32][33];
    __shared__ float vsh[32];
    __shared__ float tinv;
    int tid = threadIdx.x;

    for (int m = 0; m < 8; m++){
        int lin = m*1024 + tid;
        Ws[lin >> 8][lin & 255] = W[lin];
    }
    __syncthreads();

    int i = tid >> 5, j = tid & 31;
    float a = 0.f;
    #pragma unroll 8
    for (int c = 0; c < 256; c++) a += Ws[i][c] * Ws[j][c];
    Ao[i][j] = a;
    Aa[i][j] = a;
    __syncthreads();

    for (int s = 0; s < 5; s++){
        float (*cur)[33] = (s & 1) ? Ab : Aa;
        float (*nxt)[33] = (s & 1) ? Aa : Ab;
        if (tid == 0){
            float t = 0.f;
            for (int k2 = 0; k2 < 32; k2++) t += cur[k2][k2];
            tinv = 1.0f / t;
        }
        __syncthreads();
        float acc = 0.f;
        #pragma unroll
        for (int k2 = 0; k2 < 32; k2++) acc += cur[i][k2] * cur[j][k2];  // symmetric
        float ti = tinv;
        nxt[i][j] = acc * ti * ti;
        __syncthreads();
    }

    // power iteration on Ab (final) by warp 0
    if (tid < 32){
        vsh[tid] = 1.0f + 0.05f * (float)tid;
        __syncwarp();
        for (int it = 0; it < 40; it++){
            float w = 0.f;
            #pragma unroll
            for (int k2 = 0; k2 < 32; k2++) w += Ab[tid][k2] * vsh[k2];
            float ss = w * w;
            #pragma unroll
            for (int off = 16; off; off >>= 1) ss += __shfl_xor_sync(0xffffffffu, ss, off);
            float sc = rsqrtf(ss);
            __syncwarp();
            vsh[tid] = w * sc;
            __syncwarp();
        }
        // Rayleigh on original A
        float w = 0.f;
        #pragma unroll
        for (int k2 = 0; k2 < 32; k2++) w += Ao[tid][k2] * vsh[k2];
        float num = vsh[tid] * w, den = vsh[tid] * vsh[tid];
        #pragma unroll
        for (int off = 16; off; off >>= 1){
            num += __shfl_xor_sync(0xffffffffu, num, off);
            den += __shfl_xor_sync(0xffffffffu, den, off);
        }
        if (tid == 0) g_sigma[blockIdx.x] = sqrtf(num / den);
    }
}

// ---------------- Gram of wv: G0 = wv wv^T (256x256) ------------------------
__global__ void gram_v_kernel(const float* __restrict__ wv){
    __shared__ float as[32][33], bs[32][33];
    int tid = threadIdx.x;
    int i0 = blockIdx.y * 32, j0 = blockIdx.x * 32;
    int li = tid >> 5, lj = tid & 31;
    float acc = 0.f;
    for (int c0 = 0; c0 < 256; c0 += 32){
        as[li][lj] = wv[(i0 + li)*256 + c0 + lj];
        bs[li][lj] = wv[(j0 + li)*256 + c0 + lj];
        __syncthreads();
        #pragma unroll
        for (int cc = 0; cc < 32; cc++) acc += as[li][cc] * bs[lj][cc];
        __syncthreads();
    }
    g_G0[(i0 + li)*256 + j0 + lj] = acc;
    if (i0 + li == j0 + lj) atomicAdd(&g_tr[0], acc);
}

// ---------------- one trace-normalized squaring of a 256x256 PSD matrix -----
__device__ __forceinline__ float* gbuf(int s){
    return (s == 0) ? g_G0 : ((s == 1) ? g_GA : g_GB);
}
__global__ void sq_v_kernel(int ssel, int dsel, int step){
    const float* src = gbuf(ssel);
    float* dst = gbuf(dsel);
    __shared__ float as[32][33], bs[32][33];
    int tid = threadIdx.x;
    int i0 = blockIdx.y * 32, j0 = blockIdx.x * 32;
    int li = tid >> 5, lj = tid & 31;
    float inv = 1.0f / g_tr[step];
    float acc = 0.f;
    for (int k0 = 0; k0 < 256; k0 += 32){
        as[li][lj] = src[(i0 + li)*256 + k0 + lj];
        bs[li][lj] = src[(j0 + li)*256 + k0 + lj];   // symmetric: row j == col j
        __syncthreads();
        #pragma unroll
        for (int kk = 0; kk < 32; kk++) acc += as[li][kk] * bs[lj][kk];
        __syncthreads();
    }
    acc = acc * inv * inv;
    dst[(i0 + li)*256 + j0 + lj] = acc;
    if (i0 + li == j0 + lj) atomicAdd(&g_tr[step + 1], acc);
}

// ---------------- power + Rayleigh for sigma_v ------------------------------
// 4 applications of M8 ~ G^256 (effective power 1024), then Rayleigh on G0.
__global__ void power_v_kernel(){
    __shared__ float vsh[256], vnew[256];
    __shared__ float rss[8], rnum[8], rden[8];
    __shared__ float nscale;
    int tid = threadIdx.x;                // 1024 threads
    int lane = tid & 31, wrp = tid >> 5;  // wrp 0..31 -> rows wrp*8..+8
    if (tid < 256) vsh[tid] = 1.0f + 0.013f * (float)tid;
    __syncthreads();

    for (int it = 0; it < 5; it++){
        const float* Mat = (it < 4) ? g_GB : g_G0;
        float part[8] = {0,0,0,0,0,0,0,0};
        #pragma unroll
        for (int m = 0; m < 8; m++){
            int k2 = lane + 32*m;
            float vk = vsh[k2];
            #pragma unroll
            for (int i = 0; i < 8; i++)
                part[i] += Mat[(wrp*8 + i)*256 + k2] * vk;
        }
        #pragma unroll
        for (int i = 0; i < 8; i++){
            float r = part[i];
            #pragma unroll
            for (int off = 16; off; off >>= 1) r += __shfl_down_sync(0xffffffffu, r, off);
            if (lane == 0) vnew[wrp*8 + i] = r;
        }
        __syncthreads();
        if (it < 4){
            if (tid < 256){
                float s2 = vnew[tid] * vnew[tid];
                #pragma unroll
                for (int off = 16; off; off >>= 1) s2 += __shfl_down_sync(0xffffffffu, s2, off);
                if ((tid & 31) == 0) rss[tid >> 5] = s2;
            }
            __syncthreads();
            if (tid == 0){
                float s2 = 0.f;
                for (int u = 0; u < 8; u++) s2 += rss[u];
                nscale = rsqrtf(s2);
            }
            __syncthreads();
            if (tid < 256) vsh[tid] = vnew[tid] * nscale;
            __syncthreads();
        } else {
            if (tid < 256){
                float nv = vsh[tid] * vnew[tid];
                float dv = vsh[tid] * vsh[tid];
                #pragma unroll
                for (int off = 16; off; off >>= 1){
                    nv += __shfl_down_sync(0xffffffffu, nv, off);
                    dv += __shfl_down_sync(0xffffffffu, dv, off);
                }
                if ((tid & 31) == 0){ rnum[tid >> 5] = nv; rden[tid >> 5] = dv; }
            }
            __syncthreads();
            if (tid == 0){
                float n = 0.f, d2 = 0.f;
                for (int u = 0; u < 8; u++){ n += rnum[u]; d2 += rden[u]; }
                g_sigma[2] = sqrtf(n / d2);
            }
        }
    }
}

// ---------------- Q/K projections: out[b][n][d] = sum_c W[d][c] x[b][c][n] --
__global__ void proj_qk_kernel(const float* __restrict__ x,
                               const float* __restrict__ wq,
                               const float* __restrict__ wk){
    const float* W = (blockIdx.z == 0) ? wq : wk;
    float* dst = (blockIdx.z == 0) ? g_Q : g_K;
    int b = blockIdx.y, n0 = blockIdx.x * 64;
    __shared__ float ws[32][33], xs[32][65];
    int tid = threadIdx.x;
    int d = tid & 31, rg = tid >> 5;     // rg 0..7 -> rows rg*8 .. +8
    float acc[8] = {0,0,0,0,0,0,0,0};
    const float* xb = x + (size_t)b * CH * NSP;
    for (int c0 = 0; c0 < 256; c0 += 32){
        #pragma unroll
        for (int m = 0; m < 4; m++){
            int lin = m*256 + tid;
            ws[lin >> 5][lin & 31] = W[(lin >> 5)*256 + c0 + (lin & 31)];
        }
        #pragma unroll
        for (int m = 0; m < 8; m++){
            int lin = m*256 + tid;
            int c = lin >> 6, n = lin & 63;
            xs[c][n] = xb[(c0 + c)*NSP + n0 + n];
        }
        __syncthreads();
        #pragma unroll
        for (int cc = 0; cc < 32; cc++){
            float wv_ = ws[d][cc];
            #pragma unroll
            for (int i = 0; i < 8; i++) acc[i] += wv_ * xs[cc][rg*8 + i];
        }
        __syncthreads();
    }
    #pragma unroll
    for (int i = 0; i < 8; i++)
        dst[(size_t)b*NSP*DQK + (size_t)(n0 + rg*8 + i)*DQK + d] = acc[i];
}

// ---------------- V projection: g_V[b][n][e] = sum_c wv[e][c] x[b][c][n] ----
__global__ void proj_v_kernel(const float* __restrict__ x,
                              const float* __restrict__ wv){
    int b = blockIdx.z, e0 = blockIdx.y * 64, n0 = blockIdx.x * 64;
    __shared__ float ws[64][33], xs[32][65];
    int tid = threadIdx.x;
    int ex = tid & 15, ny = tid >> 4;    // e = e0 + ex*4 + j ; n = n0 + ny*4 + i
    float acc[4][4] = {};
    const float* xb = x + (size_t)b * CH * NSP;
    for (int c0 = 0; c0 < 256; c0 += 32){
        #pragma unroll
        for (int m = 0; m < 8; m++){
            int lin = m*256 + tid;
            ws[lin >> 5][lin & 31] = wv[(e0 + (lin >> 5))*256 + c0 + (lin & 31)];
        }
        #pragma unroll
        for (int m = 0; m < 8; m++){
            int lin = m*256 + tid;
            int c = lin >> 6, n = lin & 63;
            xs[c][n] = xb[(c0 + c)*NSP + n0 + n];
        }
        __syncthreads();
        #pragma unroll
        for (int cc = 0; cc < 32; cc++){
            float er[4], xr[4];
            #pragma unroll
            for (int jc = 0; jc < 4; jc++) er[jc] = ws[ex*4 + jc][cc];
            #pragma unroll
            for (int i = 0; i < 4; i++) xr[i] = xs[cc][ny*4 + i];
            #pragma unroll
            for (int i = 0; i < 4; i++)
                #pragma unroll
                for (int jc = 0; jc < 4; jc++)
                    acc[i][jc] += xr[i] * er[jc];
        }
        __syncthreads();
    }
    #pragma unroll
    for (int i = 0; i < 4; i++){
        float4 o = make_float4(acc[i][0], acc[i][1], acc[i][2], acc[i][3]);
        *(float4*)&g_V[(size_t)b*NSP*CH + (size_t)(n0 + ny*4 + i)*CH + e0 + ex*4] = o;
    }
}

// ---------------- flash attention + residual --------------------------------
__global__ void __launch_bounds__(256)
flash_kernel(const float* __restrict__ x, const float* __restrict__ gamma,
             float* __restrict__ out){
    __shared__ float Qs[64][33], Ks[64][33], Ss[64][65];
    __shared__ float mrow[64], lrow[64], arow[64];
    int tid = threadIdx.x;
    int b = blockIdx.y, i0 = blockIdx.x * 64;
    int tx = tid & 31, ty = tid >> 5;

    float lscale = 1.0f / (g_sigma[0] * g_sigma[1] * sqrtf((float)DQK));

    const float* Qg = g_Q + (size_t)b*NSP*DQK + (size_t)i0*DQK;
    #pragma unroll
    for (int m = 0; m < 8; m++){
        int lin = m*256 + tid;
        Qs[lin >> 5][lin & 31] = Qg[lin];
    }
    if (tid < 64){ mrow[tid] = -INFINITY; lrow[tid] = 0.f; }

    unsigned long long acc[8][4];
    #pragma unroll
    for (int ii = 0; ii < 8; ii++)
        #pragma unroll
        for (int k2 = 0; k2 < 4; k2++) acc[ii][k2] = 0ull;
    __syncthreads();

    const float* Kgb = g_K + (size_t)b*NSP*DQK;
    const float* Vgb = g_V + (size_t)b*NSP*CH;
    int rid = tid >> 4, cid = tid & 15;

    for (int jt = 0; jt < 64; jt++){
        int j0 = jt * 64;
        // stage K tile
        const float* Kg = Kgb + (size_t)j0*DQK;
        #pragma unroll
        for (int m = 0; m < 8; m++){
            int lin = m*256 + tid;
            Ks[lin >> 5][lin & 31] = Kg[lin];
        }
        __syncthreads();

        // S = (Q K^T) * lscale  (4x4 per thread)
        {
            float s[4][4] = {};
            #pragma unroll
            for (int d = 0; d < 32; d++){
                float qr[4], kc[4];
                #pragma unroll
                for (int ii = 0; ii < 4; ii++) qr[ii] = Qs[rid*4 + ii][d];
                #pragma unroll
                for (int jj = 0; jj < 4; jj++) kc[jj] = Ks[cid*4 + jj][d];
                #pragma unroll
                for (int ii = 0; ii < 4; ii++)
                    #pragma unroll
                    for (int jj = 0; jj < 4; jj++)
                        s[ii][jj] += qr[ii] * kc[jj];
            }
            #pragma unroll
            for (int ii = 0; ii < 4; ii++)
                #pragma unroll
                for (int jj = 0; jj < 4; jj++)
                    Ss[rid*4 + ii][cid*4 + jj] = s[ii][jj] * lscale;
        }
        __syncthreads();

        // streaming softmax (4 threads per row)
        {
            int row = tid >> 2, g = tid & 3;
            float mx = -INFINITY;
            #pragma unroll
            for (int c = 0; c < 16; c++) mx = fmaxf(mx, Ss[row][g*16 + c]);
            mx = fmaxf(mx, __shfl_xor_sync(0xffffffffu, mx, 1));
            mx = fmaxf(mx, __shfl_xor_sync(0xffffffffu, mx, 2));
            float mold = mrow[row];
            float mnew = fmaxf(mold, mx);
            float sum = 0.f;
            #pragma unroll
            for (int c = 0; c < 16; c++){
                float p = __expf(Ss[row][g*16 + c] - mnew);
                Ss[row][g*16 + c] = p;
                sum += p;
            }
            sum += __shfl_xor_sync(0xffffffffu, sum, 1);
            sum += __shfl_xor_sync(0xffffffffu, sum, 2);
            if (g == 0){
                float al = __expf(mold - mnew);
                lrow[row] = lrow[row] * al + sum;
                mrow[row] = mnew;
                arow[row] = al;
            }
        }
        __syncthreads();

        // O = O*alpha + P V   (packed f32x2; V streamed from gmem/L1)
        {
            #pragma unroll
            for (int ii = 0; ii < 8; ii++){
                float al = arow[ty*8 + ii];
                unsigned long long a2 = pk2(al, al);
                #pragma unroll
                for (int k2 = 0; k2 < 4; k2++) acc[ii][k2] = fmul2(acc[ii][k2], a2);
            }
            const float* Vt = Vgb + (size_t)j0*CH + 2*tx;
            #pragma unroll 2
            for (int jj = 0; jj < 64; jj++){
                unsigned long long v[4];
                #pragma unroll
                for (int k2 = 0; k2 < 4; k2++)
                    v[k2] = *(const unsigned long long*)(Vt + (size_t)jj*CH + 64*k2);
                #pragma unroll
                for (int ii = 0; ii < 8; ii++){
                    float p = Ss[ty*8 + ii][jj];
                    unsigned long long p2 = pk2(p, p);
                    #pragma unroll
                    for (int k2 = 0; k2 < 4; k2++)
                        acc[ii][k2] = ffma2(v[k2], p2, acc[ii][k2]);
                }
            }
        }
        __syncthreads();
    }

    // epilogue: out = x + (gamma/sigma_v) * O / l
    float oscale = gamma[0] / g_sigma[2];
    float linv[8];
    #pragma unroll
    for (int ii = 0; ii < 8; ii++) linv[ii] = oscale / lrow[ty*8 + ii];

    size_t base_n = (size_t)i0 + ty*8;
    #pragma unroll
    for (int k2 = 0; k2 < 4; k2++){
        float lo[8], hi[8];
        #pragma unroll
        for (int ii = 0; ii < 8; ii++) upk2(acc[ii][k2], lo[ii], hi[ii]);
        #pragma unroll
        for (int h = 0; h < 2; h++){
            int e = 64*k2 + 2*tx + h;
            size_t idx = (size_t)b*CH*NSP + (size_t)e*NSP + base_n;
            float vals[8];
            #pragma unroll
            for (int ii = 0; ii < 8; ii++)
                vals[ii] = (h ? hi[ii] : lo[ii]) * linv[ii];
            float4 x0 = *(const float4*)&x[idx];
            float4 x1 = *(const float4*)&x[idx + 4];
            float4 o0 = make_float4(x0.x + vals[0], x0.y + vals[1],
                                    x0.z + vals[2], x0.w + vals[3]);
            float4 o1 = make_float4(x1.x + vals[4], x1.y + vals[5],
                                    x1.z + vals[6], x1.w + vals[7]);
            *(float4*)&out[idx]     = o0;
            *(float4*)&out[idx + 4] = o1;
        }
    }
}

// ---------------- launch ----------------------------------------------------
extern "C" void kernel_launch(void* const* d_in, const int* in_sizes, int n_in,
                              void* d_out, int out_size){
    (void)in_sizes; (void)n_in; (void)out_size;
    const float* x     = (const float*)d_in[0];
    const float* wq    = (const float*)d_in[1];
    const float* wk    = (const float*)d_in[2];
    const float* wv    = (const float*)d_in[3];
    const float* gamma = (const float*)d_in[4];
    float* out = (float*)d_out;

    init_kernel<<<1, 32>>>();
    sigma_qk_kernel<<<2, 1024>>>(wq, wk);
    gram_v_kernel<<<dim3(8, 8), 1024>>>(wv);
    // 8 trace-normalized squarings: final matrix ~ G^256 in g_GB
    sq_v_kernel<<<dim3(8, 8), 1024>>>(0, 1, 0);
    sq_v_kernel<<<dim3(8, 8), 1024>>>(1, 2, 1);
    sq_v_kernel<<<dim3(8, 8), 1024>>>(2, 1, 2);
    sq_v_kernel<<<dim3(8, 8), 1024>>>(1, 2, 3);
    sq_v_kernel<<<dim3(8, 8), 1024>>>(2, 1, 4);
    sq_v_kernel<<<dim3(8, 8), 1024>>>(1, 2, 5);
    sq_v_kernel<<<dim3(8, 8), 1024>>>(2, 1, 6);
    sq_v_kernel<<<dim3(8, 8), 1024>>>(1, 2, 7);
    power_v_kernel<<<1, 1024>>>();

    proj_qk_kernel<<<dim3(NSP/64, BATCH, 2), 256>>>(x, wq, wk);
    proj_v_kernel<<<dim3(NSP/64, CH/64, BATCH), 256>>>(x, wv);
    flash_kernel<<<dim3(NSP/64, BATCH), 256>>>(x, gamma, out);
}

// round 6
// speedup vs baseline: 1.3169x; 1.3169x over previous
#include <cuda_runtime.h>
#include <math.h>
#include <stdint.h>

#define BATCH 4
#define CH    256
#define NSP   4096
#define DQK   32

// ---------------- scratch (__device__ globals: no runtime allocation) -------
__device__ __align__(256) float g_Q[BATCH*NSP*DQK];   // [b][n][d]
__device__ __align__(256) float g_K[BATCH*NSP*DQK];   // [b][n][d]
__device__ __align__(256) float g_V[BATCH*NSP*CH];    // [b][n][e]
__device__ __align__(256) float g_G0[CH*CH];
__device__ __align__(256) float g_GA[CH*CH];
__device__ __align__(256) float g_GB[CH*CH];
__device__ float g_tr[16];
__device__ float g_sigma[4];   // [0]=sigma_q [1]=sigma_k [2]=sigma_v

// ---------------- packed f32x2 helpers (Blackwell) --------------------------
__device__ __forceinline__ unsigned long long pk2(float lo, float hi){
    unsigned long long r;
    asm("mov.b64 %0, {%1, %2};" : "=l"(r) : "f"(lo), "f"(hi));
    return r;
}
__device__ __forceinline__ void upk2(unsigned long long a, float& lo, float& hi){
    asm("mov.b64 {%0, %1}, %2;" : "=f"(lo), "=f"(hi) : "l"(a));
}
__device__ __forceinline__ unsigned long long ffma2(unsigned long long a,
                                                    unsigned long long b,
                                                    unsigned long long c){
    unsigned long long d;
    asm("fma.rn.f32x2 %0, %1, %2, %3;" : "=l"(d) : "l"(a), "l"(b), "l"(c));
    return d;
}
__device__ __forceinline__ unsigned long long fmul2(unsigned long long a,
                                                    unsigned long long b){
    unsigned long long d;
    asm("mul.rn.f32x2 %0, %1, %2;" : "=l"(d) : "l"(a), "l"(b));
    return d;
}

// ---------------- cp.async helpers ------------------------------------------
__device__ __forceinline__ void cpa16(const float* dst, const float* src){
    uint32_t d = (uint32_t)__cvta_generic_to_shared(dst);
    asm volatile("cp.async.cg.shared.global [%0], [%1], 16;"
                 :: "r"(d), "l"(src) : "memory");
}
#define CP_COMMIT() asm volatile("cp.async.commit_group;" ::: "memory")
#define CP_WAIT(n)  asm volatile("cp.async.wait_group %0;" :: "n"(n) : "memory")

// ---------------- init ------------------------------------------------------
__global__ void init_kernel(){
    if (threadIdx.x < 16) g_tr[threadIdx.x] = 0.0f;
}

// ---------------- sigma for wq / wk (32x256) --------------------------------
__global__ void sigma_qk_kernel(const float* __restrict__ wq,
                                const float* __restrict__ wk){
    const float* W = (blockIdx.x == 0) ? wq : wk;
    __shared__ float Ws[32][257];
    __shared__ float Ao[32][33];
    __shared__ float Aa[32][33];
    __shared__ float Ab[32][33];
    __shared__ float vsh[32];
    __shared__ float tinv;
    int tid = threadIdx.x;

    for (int m = 0; m < 8; m++){
        int lin = m*1024 + tid;
        Ws[lin >> 8][lin & 255] = W[lin];
    }
    __syncthreads();

    int i = tid >> 5, j = tid & 31;
    float a = 0.f;
    #pragma unroll 8
    for (int c = 0; c < 256; c++) a += Ws[i][c] * Ws[j][c];
    Ao[i][j] = a;
    Aa[i][j] = a;
    __syncthreads();

    for (int s = 0; s < 5; s++){
        float (*cur)[33] = (s & 1) ? Ab : Aa;
        float (*nxt)[33] = (s & 1) ? Aa : Ab;
        if (tid == 0){
            float t = 0.f;
            for (int k2 = 0; k2 < 32; k2++) t += cur[k2][k2];
            tinv = 1.0f / t;
        }
        __syncthreads();
        float acc = 0.f;
        #pragma unroll
        for (int k2 = 0; k2 < 32; k2++) acc += cur[i][k2] * cur[j][k2];
        float ti = tinv;
        nxt[i][j] = acc * ti * ti;
        __syncthreads();
    }

    if (tid < 32){
        vsh[tid] = 1.0f + 0.05f * (float)tid;
        __syncwarp();
        for (int it = 0; it < 40; it++){
            float w = 0.f;
            #pragma unroll
            for (int k2 = 0; k2 < 32; k2++) w += Ab[tid][k2] * vsh[k2];
            float ss = w * w;
            #pragma unroll
            for (int off = 16; off; off >>= 1) ss += __shfl_xor_sync(0xffffffffu, ss, off);
            float sc = rsqrtf(ss);
            __syncwarp();
            vsh[tid] = w * sc;
            __syncwarp();
        }
        float w = 0.f;
        #pragma unroll
        for (int k2 = 0; k2 < 32; k2++) w += Ao[tid][k2] * vsh[k2];
        float num = vsh[tid] * w, den = vsh[tid] * vsh[tid];
        #pragma unroll
        for (int off = 16; off; off >>= 1){
            num += __shfl_xor_sync(0xffffffffu, num, off);
            den += __shfl_xor_sync(0xffffffffu, den, off);
        }
        if (tid == 0) g_sigma[blockIdx.x] = sqrtf(num / den);
    }
}

// ---------------- Gram of wv: G0 = wv wv^T (256x256) ------------------------
__global__ void gram_v_kernel(const float* __restrict__ wv){
    __shared__ float as[32][33], bs[32][33];
    int tid = threadIdx.x;
    int i0 = blockIdx.y * 32, j0 = blockIdx.x * 32;
    int li = tid >> 5, lj = tid & 31;
    float acc = 0.f;
    for (int c0 = 0; c0 < 256; c0 += 32){
        as[li][lj] = wv[(i0 + li)*256 + c0 + lj];
        bs[li][lj] = wv[(j0 + li)*256 + c0 + lj];
        __syncthreads();
        #pragma unroll
        for (int cc = 0; cc < 32; cc++) acc += as[li][cc] * bs[lj][cc];
        __syncthreads();
    }
    g_G0[(i0 + li)*256 + j0 + lj] = acc;
    if (i0 + li == j0 + lj) atomicAdd(&g_tr[0], acc);
}

// ---------------- one trace-normalized squaring of a 256x256 PSD matrix -----
__device__ __forceinline__ float* gbuf(int s){
    return (s == 0) ? g_G0 : ((s == 1) ? g_GA : g_GB);
}
__global__ void sq_v_kernel(int ssel, int dsel, int step){
    const float* src = gbuf(ssel);
    float* dst = gbuf(dsel);
    __shared__ float as[32][33], bs[32][33];
    int tid = threadIdx.x;
    int i0 = blockIdx.y * 32, j0 = blockIdx.x * 32;
    int li = tid >> 5, lj = tid & 31;
    float inv = 1.0f / g_tr[step];
    float acc = 0.f;
    for (int k0 = 0; k0 < 256; k0 += 32){
        as[li][lj] = src[(i0 + li)*256 + k0 + lj];
        bs[li][lj] = src[(j0 + li)*256 + k0 + lj];
        __syncthreads();
        #pragma unroll
        for (int kk = 0; kk < 32; kk++) acc += as[li][kk] * bs[lj][kk];
        __syncthreads();
    }
    acc = acc * inv * inv;
    dst[(i0 + li)*256 + j0 + lj] = acc;
    if (i0 + li == j0 + lj) atomicAdd(&g_tr[step + 1], acc);
}

// ---------------- power + Rayleigh for sigma_v ------------------------------
__global__ void power_v_kernel(){
    __shared__ float vsh[256], vnew[256];
    __shared__ float rss[8], rnum[8], rden[8];
    __shared__ float nscale;
    int tid = threadIdx.x;                // 1024 threads
    int lane = tid & 31, wrp = tid >> 5;
    if (tid < 256) vsh[tid] = 1.0f + 0.013f * (float)tid;
    __syncthreads();

    for (int it = 0; it < 9; it++){
        const float* Mat = (it < 8) ? g_GB : g_G0;
        float part[8] = {0,0,0,0,0,0,0,0};
        #pragma unroll
        for (int m = 0; m < 8; m++){
            int k2 = lane + 32*m;
            float vk = vsh[k2];
            #pragma unroll
            for (int i = 0; i < 8; i++)
                part[i] += Mat[(wrp*8 + i)*256 + k2] * vk;
        }
        #pragma unroll
        for (int i = 0; i < 8; i++){
            float r = part[i];
            #pragma unroll
            for (int off = 16; off; off >>= 1) r += __shfl_down_sync(0xffffffffu, r, off);
            if (lane == 0) vnew[wrp*8 + i] = r;
        }
        __syncthreads();
        if (it < 8){
            if (tid < 256){
                float s2 = vnew[tid] * vnew[tid];
                #pragma unroll
                for (int off = 16; off; off >>= 1) s2 += __shfl_down_sync(0xffffffffu, s2, off);
                if ((tid & 31) == 0) rss[tid >> 5] = s2;
            }
            __syncthreads();
            if (tid == 0){
                float s2 = 0.f;
                for (int u = 0; u < 8; u++) s2 += rss[u];
                nscale = rsqrtf(s2);
            }
            __syncthreads();
            if (tid < 256) vsh[tid] = vnew[tid] * nscale;
            __syncthreads();
        } else {
            if (tid < 256){
                float nv = vsh[tid] * vnew[tid];
                float dv = vsh[tid] * vsh[tid];
                #pragma unroll
                for (int off = 16; off; off >>= 1){
                    nv += __shfl_down_sync(0xffffffffu, nv, off);
                    dv += __shfl_down_sync(0xffffffffu, dv, off);
                }
                if ((tid & 31) == 0){ rnum[tid >> 5] = nv; rden[tid >> 5] = dv; }
            }
            __syncthreads();
            if (tid == 0){
                float n = 0.f, d2 = 0.f;
                for (int u = 0; u < 8; u++){ n += rnum[u]; d2 += rden[u]; }
                g_sigma[2] = sqrtf(n / d2);
            }
        }
    }
}

// ---------------- Q/K projections: out[b][n][d] = sum_c W[d][c] x[b][c][n] --
__global__ void proj_qk_kernel(const float* __restrict__ x,
                               const float* __restrict__ wq,
                               const float* __restrict__ wk){
    const float* W = (blockIdx.z == 0) ? wq : wk;
    float* dst = (blockIdx.z == 0) ? g_Q : g_K;
    int b = blockIdx.y, n0 = blockIdx.x * 64;
    __shared__ float ws[32][33], xs[32][65];
    int tid = threadIdx.x;
    int d = tid & 31, rg = tid >> 5;
    float acc[8] = {0,0,0,0,0,0,0,0};
    const float* xb = x + (size_t)b * CH * NSP;
    for (int c0 = 0; c0 < 256; c0 += 32){
        #pragma unroll
        for (int m = 0; m < 4; m++){
            int lin = m*256 + tid;
            ws[lin >> 5][lin & 31] = W[(lin >> 5)*256 + c0 + (lin & 31)];
        }
        #pragma unroll
        for (int m = 0; m < 8; m++){
            int lin = m*256 + tid;
            int c = lin >> 6, n = lin & 63;
            xs[c][n] = xb[(c0 + c)*NSP + n0 + n];
        }
        __syncthreads();
        #pragma unroll
        for (int cc = 0; cc < 32; cc++){
            float wv_ = ws[d][cc];
            #pragma unroll
            for (int i = 0; i < 8; i++) acc[i] += wv_ * xs[cc][rg*8 + i];
        }
        __syncthreads();
    }
    #pragma unroll
    for (int i = 0; i < 8; i++)
        dst[(size_t)b*NSP*DQK + (size_t)(n0 + rg*8 + i)*DQK + d] = acc[i];
}

// ---------------- V projection: g_V[b][n][e] = sum_c wv[e][c] x[b][c][n] ----
__global__ void proj_v_kernel(const float* __restrict__ x,
                              const float* __restrict__ wv){
    int b = blockIdx.z, e0 = blockIdx.y * 64, n0 = blockIdx.x * 64;
    __shared__ float ws[64][33], xs[32][65];
    int tid = threadIdx.x;
    int ex = tid & 15, ny = tid >> 4;
    float acc[4][4] = {};
    const float* xb = x + (size_t)b * CH * NSP;
    for (int c0 = 0; c0 < 256; c0 += 32){
        #pragma unroll
        for (int m = 0; m < 8; m++){
            int lin = m*256 + tid;
            ws[lin >> 5][lin & 31] = wv[(e0 + (lin >> 5))*256 + c0 + (lin & 31)];
        }
        #pragma unroll
        for (int m = 0; m < 8; m++){
            int lin = m*256 + tid;
            int c = lin >> 6, n = lin & 63;
            xs[c][n] = xb[(c0 + c)*NSP + n0 + n];
        }
        __syncthreads();
        #pragma unroll
        for (int cc = 0; cc < 32; cc++){
            float er[4], xr[4];
            #pragma unroll
            for (int jc = 0; jc < 4; jc++) er[jc] = ws[ex*4 + jc][cc];
            #pragma unroll
            for (int i = 0; i < 4; i++) xr[i] = xs[cc][ny*4 + i];
            #pragma unroll
            for (int i = 0; i < 4; i++)
                #pragma unroll
                for (int jc = 0; jc < 4; jc++)
                    acc[i][jc] += xr[i] * er[jc];
        }
        __syncthreads();
    }
    #pragma unroll
    for (int i = 0; i < 4; i++){
        float4 o = make_float4(acc[i][0], acc[i][1], acc[i][2], acc[i][3]);
        *(float4*)&g_V[(size_t)b*NSP*CH + (size_t)(n0 + ny*4 + i)*CH + e0 + ex*4] = o;
    }
}

// ---------------- flash attention + residual --------------------------------
// Dynamic smem layout (floats):
//   Qs  @ 0      [64][36]      (2304)
//   Ks  @ 2304   [2][64][36]   (4608)
//   Pd  @ 6912   [64][132]     (8448)  P stored duplicated: Pd[col][2r]=Pd[col][2r+1]
//   Vsm @ 15360  [2][16][256]  (8192)
//   mrow@ 23552, lrow@ 23616, arow@ 23680   -> total 23744 floats = 94976 B
#define FLASH_SMEM 94976

__global__ void __launch_bounds__(256, 2)
flash_kernel(const float* __restrict__ x, const float* __restrict__ gamma,
             float* __restrict__ out){
    extern __shared__ float sm[];
    float* Qs   = sm;
    float* Ks   = sm + 2304;
    float* Pd   = sm + 6912;
    float* Vsm  = sm + 15360;
    float* mrow = sm + 23552;
    float* lrow = sm + 23616;
    float* arow = sm + 23680;

    int tid = threadIdx.x;
    int b = blockIdx.y, i0 = blockIdx.x * 64;
    int tx = tid & 31, ty = tid >> 5;
    int rid = tid >> 4, cid = tid & 15;

    const float* Qg  = g_Q + (size_t)b*NSP*DQK + (size_t)i0*DQK;
    const float* Kgb = g_K + (size_t)b*NSP*DQK;
    const float* Vgb = g_V + (size_t)b*NSP*CH;

    float lscale = 1.0f / (g_sigma[0] * g_sigma[1] * sqrtf((float)DQK));

    // load Q tile (plain loads, once)
    #pragma unroll
    for (int i = 0; i < 2; i++){
        int f = i*256 + tid;
        int r = f >> 3, q = f & 7;
        float4 v = *(const float4*)(Qg + r*32 + q*4);
        *(float4*)(Qs + r*36 + q*4) = v;
    }
    if (tid < 64){ mrow[tid] = -INFINITY; lrow[tid] = 0.f; }

    unsigned long long acc[8][4];
    #pragma unroll
    for (int ii = 0; ii < 8; ii++)
        #pragma unroll
        for (int k2 = 0; k2 < 4; k2++) acc[ii][k2] = 0ull;

    // prefetch K tile 0
    #pragma unroll
    for (int i = 0; i < 2; i++){
        int f = i*256 + tid;
        int r = f >> 3, q = f & 7;
        cpa16(Ks + r*36 + q*4, Kgb + (size_t)r*DQK + q*4);
    }
    CP_COMMIT();

    for (int jt = 0; jt < 64; jt++){
        int kb = jt & 1;
        int j0 = jt * 64;

        // issue V chunks 0 and 1 of this tile (16 rows x 256 floats each)
        #pragma unroll
        for (int c = 0; c < 2; c++){
            #pragma unroll
            for (int i = 0; i < 4; i++){
                int f = i*256 + tid;
                int r = f >> 6, q = f & 63;          // r in [0,16), q in [0,64)
                cpa16(Vsm + c*4096 + r*256 + q*4,
                      Vgb + (size_t)(j0 + c*16 + r)*CH + q*4);
            }
            CP_COMMIT();
        }

        CP_WAIT(2);          // K(jt) done (committed before the two V groups)
        __syncthreads();     // Ks visible

        // S = Q K^T * lscale, written duplicated into Pd
        {
            const float* Kb = Ks + kb*2304;
            float s[4][4] = {};
            #pragma unroll
            for (int d4 = 0; d4 < 8; d4++){
                float4 q4[4], k4[4];
                #pragma unroll
                for (int ii = 0; ii < 4; ii++)
                    q4[ii] = *(const float4*)(Qs + (rid*4 + ii)*36 + d4*4);
                #pragma unroll
                for (int jj = 0; jj < 4; jj++)
                    k4[jj] = *(const float4*)(Kb + (cid*4 + jj)*36 + d4*4);
                #pragma unroll
                for (int ii = 0; ii < 4; ii++)
                    #pragma unroll
                    for (int jj = 0; jj < 4; jj++){
                        s[ii][jj] += q4[ii].x * k4[jj].x + q4[ii].y * k4[jj].y
                                   + q4[ii].z * k4[jj].z + q4[ii].w * k4[jj].w;
                    }
            }
            #pragma unroll
            for (int ii = 0; ii < 4; ii++)
                #pragma unroll
                for (int jj = 0; jj < 4; jj++){
                    float v = s[ii][jj] * lscale;
                    *(unsigned long long*)(Pd + (cid*4 + jj)*132 + 2*(rid*4 + ii))
                        = pk2(v, v);
                }
        }

        // prefetch next K tile (wraps harmlessly at jt=63 to keep group counts uniform)
        {
            int nj = ((jt + 1) & 63) * 64;
            #pragma unroll
            for (int i = 0; i < 2; i++){
                int f = i*256 + tid;
                int r = f >> 3, q = f & 7;
                cpa16(Ks + (kb ^ 1)*2304 + r*36 + q*4,
                      Kgb + (size_t)(nj + r)*DQK + q*4);
            }
            CP_COMMIT();
        }
        __syncthreads();     // raw S complete in Pd

        // streaming softmax (4 threads per row)
        {
            int r = tid >> 2, g = tid & 3;
            float mx = -INFINITY;
            #pragma unroll
            for (int c = 0; c < 16; c++)
                mx = fmaxf(mx, Pd[(g*16 + c)*132 + 2*r]);
            mx = fmaxf(mx, __shfl_xor_sync(0xffffffffu, mx, 1));
            mx = fmaxf(mx, __shfl_xor_sync(0xffffffffu, mx, 2));
            float mold = mrow[r];
            float mnew = fmaxf(mold, mx);
            float sum = 0.f;
            #pragma unroll
            for (int c = 0; c < 16; c++){
                float p = __expf(Pd[(g*16 + c)*132 + 2*r] - mnew);
                *(unsigned long long*)(Pd + (g*16 + c)*132 + 2*r) = pk2(p, p);
                sum += p;
            }
            sum += __shfl_xor_sync(0xffffffffu, sum, 1);
            sum += __shfl_xor_sync(0xffffffffu, sum, 2);
            if (g == 0){
                float al = __expf(mold - mnew);
                lrow[r] = lrow[r] * al + sum;
                mrow[r] = mnew;
                arow[r] = al;
            }
        }
        __syncthreads();     // exp(P) complete

        // rescale accumulator (skip when all alphas are exactly 1)
        {
            float al8[8]; bool allone = true;
            #pragma unroll
            for (int ii = 0; ii < 8; ii++){
                al8[ii] = arow[ty*8 + ii];
                allone = allone && (al8[ii] == 1.0f);
            }
            if (!allone){
                #pragma unroll
                for (int ii = 0; ii < 8; ii++){
                    unsigned long long a2 = pk2(al8[ii], al8[ii]);
                    #pragma unroll
                    for (int k2 = 0; k2 < 4; k2++)
                        acc[ii][k2] = fmul2(acc[ii][k2], a2);
                }
            }
        }

        // PV over 4 chunks of 16 keys, double-buffered through smem.
        // Group completion order: V(c), V(c+1), Knext, V(c+2), V(c+3).
        #pragma unroll
        for (int c = 0; c < 4; c++){
            if (c <= 1)      { CP_WAIT(2); }   // chunk c ready
            else if (c == 2) { CP_WAIT(1); }
            else             { CP_WAIT(0); }
            __syncthreads();                    // chunk data visible to all

            const float* Vb = Vsm + (c & 1)*4096;
            #pragma unroll 2
            for (int jj = 0; jj < 16; jj++){
                const ulonglong2* pp =
                    (const ulonglong2*)(Pd + (c*16 + jj)*132 + ty*16);
                ulonglong2 pA = pp[0], pB = pp[1], pC = pp[2], pD = pp[3];
                unsigned long long p2[8] = {pA.x, pA.y, pB.x, pB.y,
                                            pC.x, pC.y, pD.x, pD.y};
                const float* vr = Vb + jj*256 + 2*tx;
                unsigned long long v0 = *(const unsigned long long*)(vr);
                unsigned long long v1 = *(const unsigned long long*)(vr + 64);
                unsigned long long v2 = *(const unsigned long long*)(vr + 128);
                unsigned long long v3 = *(const unsigned long long*)(vr + 192);
                #pragma unroll
                for (int ii = 0; ii < 8; ii++){
                    acc[ii][0] = ffma2(v0, p2[ii], acc[ii][0]);
                    acc[ii][1] = ffma2(v1, p2[ii], acc[ii][1]);
                    acc[ii][2] = ffma2(v2, p2[ii], acc[ii][2]);
                    acc[ii][3] = ffma2(v3, p2[ii], acc[ii][3]);
                }
            }

            // after ALL warps finished reading buffer (c&1), refill it with chunk c+2
            if (c < 2){
                __syncthreads();
                #pragma unroll
                for (int i = 0; i < 4; i++){
                    int f = i*256 + tid;
                    int r = f >> 6, q = f & 63;
                    cpa16(Vsm + (c & 1)*4096 + r*256 + q*4,
                          Vgb + (size_t)(j0 + (c + 2)*16 + r)*CH + q*4);
                }
                CP_COMMIT();
            }
        }
        __syncthreads();   // all warps done before next tile overwrites Pd/Vsm
    }

    // epilogue: out = x + (gamma/sigma_v) * O / l
    float oscale = gamma[0] / g_sigma[2];
    float linv[8];
    #pragma unroll
    for (int ii = 0; ii < 8; ii++) linv[ii] = oscale / lrow[ty*8 + ii];

    size_t base_n = (size_t)i0 + ty*8;
    #pragma unroll
    for (int k2 = 0; k2 < 4; k2++){
        float lo[8], hi[8];
        #pragma unroll
        for (int ii = 0; ii < 8; ii++) upk2(acc[ii][k2], lo[ii], hi[ii]);
        #pragma unroll
        for (int h = 0; h < 2; h++){
            int e = 64*k2 + 2*tx + h;
            size_t idx = (size_t)b*CH*NSP + (size_t)e*NSP + base_n;
            float vals[8];
            #pragma unroll
            for (int ii = 0; ii < 8; ii++)
                vals[ii] = (h ? hi[ii] : lo[ii]) * linv[ii];
            float4 x0 = *(const float4*)&x[idx];
            float4 x1 = *(const float4*)&x[idx + 4];
            float4 o0 = make_float4(x0.x + vals[0], x0.y + vals[1],
                                    x0.z + vals[2], x0.w + vals[3]);
            float4 o1 = make_float4(x1.x + vals[4], x1.y + vals[5],
                                    x1.z + vals[6], x1.w + vals[7]);
            *(float4*)&out[idx]     = o0;
            *(float4*)&out[idx + 4] = o1;
        }
    }
}

// ---------------- launch ----------------------------------------------------
extern "C" void kernel_launch(void* const* d_in, const int* in_sizes, int n_in,
                              void* d_out, int out_size){
    (void)in_sizes; (void)n_in; (void)out_size;
    const float* x     = (const float*)d_in[0];
    const float* wq    = (const float*)d_in[1];
    const float* wk    = (const float*)d_in[2];
    const float* wv    = (const float*)d_in[3];
    const float* gamma = (const float*)d_in[4];
    float* out = (float*)d_out;

    cudaFuncSetAttribute(flash_kernel,
                         cudaFuncAttributeMaxDynamicSharedMemorySize, FLASH_SMEM);

    init_kernel<<<1, 32>>>();
    sigma_qk_kernel<<<2, 1024>>>(wq, wk);
    gram_v_kernel<<<dim3(8, 8), 1024>>>(wv);
    // 6 trace-normalized squarings: final matrix ~ G^64 in g_GB
    sq_v_kernel<<<dim3(8, 8), 1024>>>(0, 1, 0);
    sq_v_kernel<<<dim3(8, 8), 1024>>>(1, 2, 1);
    sq_v_kernel<<<dim3(8, 8), 1024>>>(2, 1, 2);
    sq_v_kernel<<<dim3(8, 8), 1024>>>(1, 2, 3);
    sq_v_kernel<<<dim3(8, 8), 1024>>>(2, 1, 4);
    sq_v_kernel<<<dim3(8, 8), 1024>>>(1, 2, 5);
    power_v_kernel<<<1, 1024>>>();

    proj_qk_kernel<<<dim3(NSP/64, BATCH, 2), 256>>>(x, wq, wk);
    proj_v_kernel<<<dim3(NSP/64, CH/64, BATCH), 256>>>(x, wv);
    flash_kernel<<<dim3(NSP/64, BATCH), 256, FLASH_SMEM>>>(x, gamma, out);
}

// round 9
// speedup vs baseline: 1.3477x; 1.0234x over previous
#include <cuda_runtime.h>
#include <math.h>
#include <stdint.h>

#define BATCH 4
#define CH    256
#define NSP   4096
#define DQK   32

// ---------------- scratch (__device__ globals: no runtime allocation) -------
__device__ __align__(256) float g_Q[BATCH*NSP*DQK];   // [b][n][d]
__device__ __align__(256) float g_K[BATCH*NSP*DQK];   // [b][n][d]
__device__ __align__(256) float g_V[BATCH*NSP*CH];    // [b][n][e]
__device__ __align__(256) float g_O[BATCH*CH*NSP];    // [b][e][n] (pre-scale)
__device__ __align__(256) float g_G0[CH*CH];
__device__ __align__(256) float g_GA[CH*CH];
__device__ __align__(256) float g_GB[CH*CH];
__device__ float g_tr[16];
__device__ float g_sigma[4];   // [0]=sigma_q [1]=sigma_k [2]=sigma_v

// ---------------- packed f32x2 helpers (Blackwell) --------------------------
__device__ __forceinline__ unsigned long long pk2(float lo, float hi){
    unsigned long long r;
    asm("mov.b64 %0, {%1, %2};" : "=l"(r) : "f"(lo), "f"(hi));
    return r;
}
__device__ __forceinline__ void upk2(unsigned long long a, float& lo, float& hi){
    asm("mov.b64 {%0, %1}, %2;" : "=f"(lo), "=f"(hi) : "l"(a));
}
__device__ __forceinline__ unsigned long long ffma2(unsigned long long a,
                                                    unsigned long long b,
                                                    unsigned long long c){
    unsigned long long d;
    asm("fma.rn.f32x2 %0, %1, %2, %3;" : "=l"(d) : "l"(a), "l"(b), "l"(c));
    return d;
}
__device__ __forceinline__ unsigned long long fmul2(unsigned long long a,
                                                    unsigned long long b){
    unsigned long long d;
    asm("mul.rn.f32x2 %0, %1, %2;" : "=l"(d) : "l"(a), "l"(b));
    return d;
}

// ---------------- cp.async helpers ------------------------------------------
__device__ __forceinline__ void cpa16(const float* dst, const float* src){
    uint32_t d = (uint32_t)__cvta_generic_to_shared(dst);
    asm volatile("cp.async.cg.shared.global [%0], [%1], 16;"
                 :: "r"(d), "l"(src) : "memory");
}
#define CP_COMMIT() asm volatile("cp.async.commit_group;" ::: "memory")
#define CP_WAIT(n)  asm volatile("cp.async.wait_group %0;" :: "n"(n) : "memory")

// ---------------- init ------------------------------------------------------
__global__ void init_kernel(){
    if (threadIdx.x < 16) g_tr[threadIdx.x] = 0.0f;
}

// ---------------- sigma for wq / wk (32x256) --------------------------------
__global__ void sigma_qk_kernel(const float* __restrict__ wq,
                                const float* __restrict__ wk){
    const float* W = (blockIdx.x == 0) ? wq : wk;
    __shared__ float Ws[32][257];
    __shared__ float Ao[32][33];
    __shared__ float Aa[32][33];
    __shared__ float Ab[32][33];
    __shared__ float vsh[32];
    __shared__ float tinv;
    int tid = threadIdx.x;

    for (int m = 0; m < 8; m++){
        int lin = m*1024 + tid;
        Ws[lin >> 8][lin & 255] = W[lin];
    }
    __syncthreads();

    int i = tid >> 5, j = tid & 31;
    float a = 0.f;
    #pragma unroll 8
    for (int c = 0; c < 256; c++) a += Ws[i][c] * Ws[j][c];
    Ao[i][j] = a;
    Aa[i][j] = a;
    __syncthreads();

    for (int s = 0; s < 5; s++){
        float (*cur)[33] = (s & 1) ? Ab : Aa;
        float (*nxt)[33] = (s & 1) ? Aa : Ab;
        if (tid == 0){
            float t = 0.f;
            for (int k2 = 0; k2 < 32; k2++) t += cur[k2][k2];
            tinv = 1.0f / t;
        }
        __syncthreads();
        float acc = 0.f;
        #pragma unroll
        for (int k2 = 0; k2 < 32; k2++) acc += cur[i][k2] * cur[j][k2];
        float ti = tinv;
        nxt[i][j] = acc * ti * ti;
        __syncthreads();
    }

    if (tid < 32){
        vsh[tid] = 1.0f + 0.05f * (float)tid;
        __syncwarp();
        for (int it = 0; it < 40; it++){
            float w = 0.f;
            #pragma unroll
            for (int k2 = 0; k2 < 32; k2++) w += Ab[tid][k2] * vsh[k2];
            float ss = w * w;
            #pragma unroll
            for (int off = 16; off; off >>= 1) ss += __shfl_xor_sync(0xffffffffu, ss, off);
            float sc = rsqrtf(ss);
            __syncwarp();
            vsh[tid] = w * sc;
            __syncwarp();
        }
        float w = 0.f;
        #pragma unroll
        for (int k2 = 0; k2 < 32; k2++) w += Ao[tid][k2] * vsh[k2];
        float num = vsh[tid] * w, den = vsh[tid] * vsh[tid];
        #pragma unroll
        for (int off = 16; off; off >>= 1){
            num += __shfl_xor_sync(0xffffffffu, num, off);
            den += __shfl_xor_sync(0xffffffffu, den, off);
        }
        if (tid == 0) g_sigma[blockIdx.x] = sqrtf(num / den);
    }
}

// ---------------- Gram of wv: G0 = wv wv^T (256x256) ------------------------
__global__ void gram_v_kernel(const float* __restrict__ wv){
    __shared__ float as[32][33], bs[32][33];
    int tid = threadIdx.x;
    int i0 = blockIdx.y * 32, j0 = blockIdx.x * 32;
    int li = tid >> 5, lj = tid & 31;
    float acc = 0.f;
    for (int c0 = 0; c0 < 256; c0 += 32){
        as[li][lj] = wv[(i0 + li)*256 + c0 + lj];
        bs[li][lj] = wv[(j0 + li)*256 + c0 + lj];
        __syncthreads();
        #pragma unroll
        for (int cc = 0; cc < 32; cc++) acc += as[li][cc] * bs[lj][cc];
        __syncthreads();
    }
    g_G0[(i0 + li)*256 + j0 + lj] = acc;
    if (i0 + li == j0 + lj) atomicAdd(&g_tr[0], acc);
}

// ---------------- one trace-normalized squaring of a 256x256 PSD matrix -----
__device__ __forceinline__ float* gbuf(int s){
    return (s == 0) ? g_G0 : ((s == 1) ? g_GA : g_GB);
}
__global__ void sq_v_kernel(int ssel, int dsel, int step){
    const float* src = gbuf(ssel);
    float* dst = gbuf(dsel);
    __shared__ float as[32][33], bs[32][33];
    int tid = threadIdx.x;
    int i0 = blockIdx.y * 32, j0 = blockIdx.x * 32;
    int li = tid >> 5, lj = tid & 31;
    float inv = 1.0f / g_tr[step];
    float acc = 0.f;
    for (int k0 = 0; k0 < 256; k0 += 32){
        as[li][lj] = src[(i0 + li)*256 + k0 + lj];
        bs[li][lj] = src[(j0 + li)*256 + k0 + lj];
        __syncthreads();
        #pragma unroll
        for (int kk = 0; kk < 32; kk++) acc += as[li][kk] * bs[lj][kk];
        __syncthreads();
    }
    acc = acc * inv * inv;
    dst[(i0 + li)*256 + j0 + lj] = acc;
    if (i0 + li == j0 + lj) atomicAdd(&g_tr[step + 1], acc);
}

// ---------------- power + Rayleigh for sigma_v ------------------------------
__global__ void power_v_kernel(){
    __shared__ float vsh[256], vnew[256];
    __shared__ float rss[8], rnum[8], rden[8];
    __shared__ float nscale;
    int tid = threadIdx.x;                // 1024 threads
    int lane = tid & 31, wrp = tid >> 5;
    if (tid < 256) vsh[tid] = 1.0f + 0.013f * (float)tid;
    __syncthreads();

    for (int it = 0; it < 9; it++){
        const float* Mat = (it < 8) ? g_GB : g_G0;
        float part[8] = {0,0,0,0,0,0,0,0};
        #pragma unroll
        for (int m = 0; m < 8; m++){
            int k2 = lane + 32*m;
            float vk = vsh[k2];
            #pragma unroll
            for (int i = 0; i < 8; i++)
                part[i] += Mat[(wrp*8 + i)*256 + k2] * vk;
        }
        #pragma unroll
        for (int i = 0; i < 8; i++){
            float r = part[i];
            #pragma unroll
            for (int off = 16; off; off >>= 1) r += __shfl_down_sync(0xffffffffu, r, off);
            if (lane == 0) vnew[wrp*8 + i] = r;
        }
        __syncthreads();
        if (it < 8){
            if (tid < 256){
                float s2 = vnew[tid] * vnew[tid];
                #pragma unroll
                for (int off = 16; off; off >>= 1) s2 += __shfl_down_sync(0xffffffffu, s2, off);
                if ((tid & 31) == 0) rss[tid >> 5] = s2;
            }
            __syncthreads();
            if (tid == 0){
                float s2 = 0.f;
                for (int u = 0; u < 8; u++) s2 += rss[u];
                nscale = rsqrtf(s2);
            }
            __syncthreads();
            if (tid < 256) vsh[tid] = vnew[tid] * nscale;
            __syncthreads();
        } else {
            if (tid < 256){
                float nv = vsh[tid] * vnew[tid];
                float dv = vsh[tid] * vsh[tid];
                #pragma unroll
                for (int off = 16; off; off >>= 1){
                    nv += __shfl_down_sync(0xffffffffu, nv, off);
                    dv += __shfl_down_sync(0xffffffffu, dv, off);
                }
                if ((tid & 31) == 0){ rnum[tid >> 5] = nv; rden[tid >> 5] = dv; }
            }
            __syncthreads();
            if (tid == 0){
                float n = 0.f, d2 = 0.f;
                for (int u = 0; u < 8; u++){ n += rnum[u]; d2 += rden[u]; }
                g_sigma[2] = sqrtf(n / d2);
            }
        }
    }
}

// ---------------- Q/K projections: out[b][n][d] = sum_c W[d][c] x[b][c][n] --
__global__ void proj_qk_kernel(const float* __restrict__ x,
                               const float* __restrict__ wq,
                               const float* __restrict__ wk){
    const float* W = (blockIdx.z == 0) ? wq : wk;
    float* dst = (blockIdx.z == 0) ? g_Q : g_K;
    int b = blockIdx.y, n0 = blockIdx.x * 64;
    __shared__ float ws[32][33], xs[32][65];
    int tid = threadIdx.x;
    int d = tid & 31, rg = tid >> 5;
    float acc[8] = {0,0,0,0,0,0,0,0};
    const float* xb = x + (size_t)b * CH * NSP;
    for (int c0 = 0; c0 < 256; c0 += 32){
        #pragma unroll
        for (int m = 0; m < 4; m++){
            int lin = m*256 + tid;
            ws[lin >> 5][lin & 31] = W[(lin >> 5)*256 + c0 + (lin & 31)];
        }
        #pragma unroll
        for (int m = 0; m < 8; m++){
            int lin = m*256 + tid;
            int c = lin >> 6, n = lin & 63;
            xs[c][n] = xb[(c0 + c)*NSP + n0 + n];
        }
        __syncthreads();
        #pragma unroll
        for (int cc = 0; cc < 32; cc++){
            float wv_ = ws[d][cc];
            #pragma unroll
            for (int i = 0; i < 8; i++) acc[i] += wv_ * xs[cc][rg*8 + i];
        }
        __syncthreads();
    }
    #pragma unroll
    for (int i = 0; i < 8; i++)
        dst[(size_t)b*NSP*DQK + (size_t)(n0 + rg*8 + i)*DQK + d] = acc[i];
}

// ---------------- V projection: g_V[b][n][e] = sum_c wv[e][c] x[b][c][n] ----
__global__ void proj_v_kernel(const float* __restrict__ x,
                              const float* __restrict__ wv){
    int b = blockIdx.z, e0 = blockIdx.y * 64, n0 = blockIdx.x * 64;
    __shared__ float ws[64][33], xs[32][65];
    int tid = threadIdx.x;
    int ex = tid & 15, ny = tid >> 4;
    float acc[4][4] = {};
    const float* xb = x + (size_t)b * CH * NSP;
    for (int c0 = 0; c0 < 256; c0 += 32){
        #pragma unroll
        for (int m = 0; m < 8; m++){
            int lin = m*256 + tid;
            ws[lin >> 5][lin & 31] = wv[(e0 + (lin >> 5))*256 + c0 + (lin & 31)];
        }
        #pragma unroll
        for (int m = 0; m < 8; m++){
            int lin = m*256 + tid;
            int c = lin >> 6, n = lin & 63;
            xs[c][n] = xb[(c0 + c)*NSP + n0 + n];
        }
        __syncthreads();
        #pragma unroll
        for (int cc = 0; cc < 32; cc++){
            float er[4], xr[4];
            #pragma unroll
            for (int jc = 0; jc < 4; jc++) er[jc] = ws[ex*4 + jc][cc];
            #pragma unroll
            for (int i = 0; i < 4; i++) xr[i] = xs[cc][ny*4 + i];
            #pragma unroll
            for (int i = 0; i < 4; i++)
                #pragma unroll
                for (int jc = 0; jc < 4; jc++)
                    acc[i][jc] += xr[i] * er[jc];
        }
        __syncthreads();
    }
    #pragma unroll
    for (int i = 0; i < 4; i++){
        float4 o = make_float4(acc[i][0], acc[i][1], acc[i][2], acc[i][3]);
        *(float4*)&g_V[(size_t)b*NSP*CH + (size_t)(n0 + ny*4 + i)*CH + e0 + ex*4] = o;
    }
}

// ---------------- flash attention (writes O/l to g_O) -----------------------
// Dynamic smem layout (floats):
//   Qs  @ 0      [64][36]       (2304)
//   Ks  @ 2304   [2][64][36]    (4608)
//   Pd  @ 6912   [64][132]      (8448)  P TRANSPOSED + duplicated:
//                                       Pd[key][2q] = Pd[key][2q+1] = P[q][key]
//   Vsm @ 15360  [3][16][256]   (12288) 3 chunk buffers (chunk3 reuses buf0)
//   mrow@ 27648, lrow@ 27712, arow@ 27776  -> total 27840 floats = 111360 B
#define FLASH_SMEM 111360

__global__ void __launch_bounds__(256, 2)
flash_kernel(float* __restrict__ Og){
    extern __shared__ float sm[];
    float* Qs   = sm;
    float* Ks   = sm + 2304;
    float* Pd   = sm + 6912;
    float* Vsm  = sm + 15360;
    float* mrow = sm + 27648;
    float* lrow = sm + 27712;
    float* arow = sm + 27776;

    int tid = threadIdx.x;
    int b = blockIdx.y, i0 = blockIdx.x * 64;
    int tx = tid & 31, ty = tid >> 5;
    int rid = tid >> 4, cid = tid & 15;

    const float* Qg  = g_Q + (size_t)b*NSP*DQK + (size_t)i0*DQK;
    const float* Kgb = g_K + (size_t)b*NSP*DQK;
    const float* Vgb = g_V + (size_t)b*NSP*CH;

    float lscale = 1.0f / (g_sigma[0] * g_sigma[1] * sqrtf((float)DQK));

    // load Q tile (plain loads, once)
    #pragma unroll
    for (int i = 0; i < 2; i++){
        int f = i*256 + tid;
        int r = f >> 3, q = f & 7;
        float4 v = *(const float4*)(Qg + r*32 + q*4);
        *(float4*)(Qs + r*36 + q*4) = v;
    }
    if (tid < 64){ mrow[tid] = -INFINITY; lrow[tid] = 0.f; }

    unsigned long long acc[8][4];
    #pragma unroll
    for (int ii = 0; ii < 8; ii++)
        #pragma unroll
        for (int k2 = 0; k2 < 4; k2++) acc[ii][k2] = 0ull;

    // prefetch K tile 0
    #pragma unroll
    for (int i = 0; i < 2; i++){
        int f = i*256 + tid;
        int r = f >> 3, q = f & 7;
        cpa16(Ks + r*36 + q*4, Kgb + (size_t)r*DQK + q*4);
    }
    CP_COMMIT();

    for (int jt = 0; jt < 64; jt++){
        int kb = jt & 1;
        int j0 = jt * 64;

        // issue V chunks 0,1,2 into buffers 0,1,2
        #pragma unroll
        for (int c = 0; c < 3; c++){
            #pragma unroll
            for (int i = 0; i < 4; i++){
                int f = i*256 + tid;
                int r = f >> 6, q = f & 63;          // r in [0,16), q in [0,64)
                cpa16(Vsm + c*4096 + r*256 + q*4,
                      Vgb + (size_t)(j0 + c*16 + r)*CH + q*4);
            }
            CP_COMMIT();
        }

        CP_WAIT(3);          // K(jt) done (oldest of 4 groups)
        __syncthreads();     // Ks visible

        // S = Q K^T * lscale -> Pd transposed+duplicated
        {
            const float* Kb = Ks + kb*2304;
            float s[4][4] = {};
            #pragma unroll
            for (int d4 = 0; d4 < 8; d4++){
                float4 q4[4], k4[4];
                #pragma unroll
                for (int ii = 0; ii < 4; ii++)
                    q4[ii] = *(const float4*)(Qs + (rid*4 + ii)*36 + d4*4);
                #pragma unroll
                for (int jj = 0; jj < 4; jj++)
                    k4[jj] = *(const float4*)(Kb + (cid*4 + jj)*36 + d4*4);
                #pragma unroll
                for (int ii = 0; ii < 4; ii++)
                    #pragma unroll
                    for (int jj = 0; jj < 4; jj++){
                        s[ii][jj] += q4[ii].x * k4[jj].x + q4[ii].y * k4[jj].y
                                   + q4[ii].z * k4[jj].z + q4[ii].w * k4[jj].w;
                    }
            }
            #pragma unroll
            for (int ii = 0; ii < 4; ii++)
                #pragma unroll
                for (int jj = 0; jj < 4; jj++){
                    float v = s[ii][jj] * lscale;
                    *(unsigned long long*)(Pd + (cid*4 + jj)*132 + 2*(rid*4 + ii))
                        = pk2(v, v);
                }
        }

        // prefetch next K tile (wraps harmlessly at jt=63)
        {
            int nj = ((jt + 1) & 63) * 64;
            #pragma unroll
            for (int i = 0; i < 2; i++){
                int f = i*256 + tid;
                int r = f >> 3, q = f & 7;
                cpa16(Ks + (kb ^ 1)*2304 + r*36 + q*4,
                      Kgb + (size_t)(nj + r)*DQK + q*4);
            }
            CP_COMMIT();
        }
        __syncthreads();     // raw S complete in Pd

        // streaming softmax (4 threads per row r = query)
        {
            int r = tid >> 2, g = tid & 3;
            float mx = -INFINITY;
            #pragma unroll
            for (int c = 0; c < 16; c++)
                mx = fmaxf(mx, Pd[(g*16 + c)*132 + 2*r]);
            mx = fmaxf(mx, __shfl_xor_sync(0xffffffffu, mx, 1));
            mx = fmaxf(mx, __shfl_xor_sync(0xffffffffu, mx, 2));
            float mold = mrow[r];
            float mnew = fmaxf(mold, mx);
            float sum = 0.f;
            #pragma unroll
            for (int c = 0; c < 16; c++){
                float p = __expf(Pd[(g*16 + c)*132 + 2*r] - mnew);
                *(unsigned long long*)(Pd + (g*16 + c)*132 + 2*r) = pk2(p, p);
                sum += p;
            }
            sum += __shfl_xor_sync(0xffffffffu, sum, 1);
            sum += __shfl_xor_sync(0xffffffffu, sum, 2);
            if (g == 0){
                float al = __expf(mold - mnew);
                lrow[r] = lrow[r] * al + sum;
                mrow[r] = mnew;
                arow[r] = al;
            }
        }

        CP_WAIT(3);          // V0 done (pending: V1,V2,Knext)
        __syncthreads();     // exp(P) + V0 visible

        // rescale accumulator (skip when all alphas are exactly 1)
        {
            float al8[8]; bool allone = true;
            #pragma unroll
            for (int ii = 0; ii < 8; ii++){
                al8[ii] = arow[ty*8 + ii];
                allone = allone && (al8[ii] == 1.0f);
            }
            if (!allone){
                #pragma unroll
                for (int ii = 0; ii < 8; ii++){
                    unsigned long long a2 = pk2(al8[ii], al8[ii]);
                    #pragma unroll
                    for (int k2 = 0; k2 < 4; k2++)
                        acc[ii][k2] = fmul2(acc[ii][k2], a2);
                }
            }
        }

        // PV over 4 chunks of 16 keys; buffers 0,1,2,0
        // Group completion order: V1, V2, Knext, V3.
        #pragma unroll
        for (int c = 0; c < 4; c++){
            if (c == 1)      { CP_WAIT(3); __syncthreads(); }  // V1
            else if (c == 2) { CP_WAIT(2); __syncthreads(); }  // V2
            else if (c == 3) { CP_WAIT(0); __syncthreads(); }  // Knext+V3

            const float* Vb = Vsm + ((c == 3) ? 0 : c)*4096;
            #pragma unroll 4
            for (int jj = 0; jj < 16; jj++){
                // P: duplicated pairs for 8 queries = 4 LDS.128 (broadcast)
                const ulonglong2* pp =
                    (const ulonglong2*)(Pd + (c*16 + jj)*132 + ty*16);
                ulonglong2 pA = pp[0], pB = pp[1], pC = pp[2], pD = pp[3];
                unsigned long long p2[8] = {pA.x, pA.y, pB.x, pB.y,
                                            pC.x, pC.y, pD.x, pD.y};
                // V: channels {4tx..4tx+3} and {128+4tx..+3} = 2 LDS.128
                const ulonglong2* va =
                    (const ulonglong2*)(Vb + jj*256 + 4*tx);
                const ulonglong2* vbp =
                    (const ulonglong2*)(Vb + jj*256 + 128 + 4*tx);
                ulonglong2 v01 = *va;
                ulonglong2 v23 = *vbp;
                #pragma unroll
                for (int ii = 0; ii < 8; ii++){
                    acc[ii][0] = ffma2(v01.x, p2[ii], acc[ii][0]);
                    acc[ii][1] = ffma2(v01.y, p2[ii], acc[ii][1]);
                    acc[ii][2] = ffma2(v23.x, p2[ii], acc[ii][2]);
                    acc[ii][3] = ffma2(v23.y, p2[ii], acc[ii][3]);
                }
            }

            // after chunk 0, refill buffer 0 with chunk 3 (all warps done with it)
            if (c == 0){
                __syncthreads();
                #pragma unroll
                for (int i = 0; i < 4; i++){
                    int f = i*256 + tid;
                    int r = f >> 6, q = f & 63;
                    cpa16(Vsm + r*256 + q*4,
                          Vgb + (size_t)(j0 + 48 + r)*CH + q*4);
                }
                CP_COMMIT();
            }
        }
        __syncthreads();   // all warps done with Pd/Vsm before next tile
    }

    // epilogue: write O/l to g_O[b][e][n]
    float linv[8];
    #pragma unroll
    for (int ii = 0; ii < 8; ii++) linv[ii] = 1.0f / lrow[ty*8 + ii];

    size_t base_n = (size_t)i0 + ty*8;
    #pragma unroll
    for (int k2 = 0; k2 < 4; k2++){
        float lo[8], hi[8];
        #pragma unroll
        for (int ii = 0; ii < 8; ii++) upk2(acc[ii][k2], lo[ii], hi[ii]);
        // acc[.][0]={4tx,4tx+1} [1]={4tx+2,4tx+3} [2]={128+4tx,..} [3]={128+4tx+2,..}
        int e_base = (k2 >> 1)*128 + 4*tx + (k2 & 1)*2;
        #pragma unroll
        for (int h = 0; h < 2; h++){
            int e = e_base + h;
            size_t idx = (size_t)b*CH*NSP + (size_t)e*NSP + base_n;
            float vals[8];
            #pragma unroll
            for (int ii = 0; ii < 8; ii++)
                vals[ii] = (h ? hi[ii] : lo[ii]) * linv[ii];
            float4 o0 = make_float4(vals[0], vals[1], vals[2], vals[3]);
            float4 o1 = make_float4(vals[4], vals[5], vals[6], vals[7]);
            *(float4*)&Og[idx]     = o0;
            *(float4*)&Og[idx + 4] = o1;
        }
    }
}

// ---------------- epilogue: out = x + (gamma/sigma_v) * O -------------------
__global__ void epilogue_kernel(const float* __restrict__ x,
                                const float* __restrict__ gamma,
                                float* __restrict__ out){
    size_t i = ((size_t)blockIdx.x * 256 + threadIdx.x) * 4;
    float s = gamma[0] / g_sigma[2];
    float4 xv = *(const float4*)&x[i];
    float4 ov = *(const float4*)&g_O[i];
    float4 r = make_float4(xv.x + s*ov.x, xv.y + s*ov.y,
                           xv.z + s*ov.z, xv.w + s*ov.w);
    *(float4*)&out[i] = r;
}

// ---------------- launch ----------------------------------------------------
extern "C" void kernel_launch(void* const* d_in, const int* in_sizes, int n_in,
                              void* d_out, int out_size){
    (void)in_sizes; (void)n_in; (void)out_size;
    const float* x     = (const float*)d_in[0];
    const float* wq    = (const float*)d_in[1];
    const float* wk    = (const float*)d_in[2];
    const float* wv    = (const float*)d_in[3];
    const float* gamma = (const float*)d_in[4];
    float* out = (float*)d_out;

    cudaFuncSetAttribute(flash_kernel,
                         cudaFuncAttributeMaxDynamicSharedMemorySize, FLASH_SMEM);

    float* Og;
    cudaGetSymbolAddress((void**)&Og, g_O);

    // launches 1-5, flash is launch #6 (ncu -s 5 -c 1 profiles it)
    init_kernel<<<1, 32>>>();
    sigma_qk_kernel<<<2, 1024>>>(wq, wk);
    proj_qk_kernel<<<dim3(NSP/64, BATCH, 2), 256>>>(x, wq, wk);
    proj_v_kernel<<<dim3(NSP/64, CH/64, BATCH), 256>>>(x, wv);
    gram_v_kernel<<<dim3(8, 8), 1024>>>(wv);
    flash_kernel<<<dim3(NSP/64, BATCH), 256, FLASH_SMEM>>>(Og);

    // sigma_v chain (independent of flash) + final epilogue
    sq_v_kernel<<<dim3(8, 8), 1024>>>(0, 1, 0);
    sq_v_kernel<<<dim3(8, 8), 1024>>>(1, 2, 1);
    sq_v_kernel<<<dim3(8, 8), 1024>>>(2, 1, 2);
    sq_v_kernel<<<dim3(8, 8), 1024>>>(1, 2, 3);
    sq_v_kernel<<<dim3(8, 8), 1024>>>(2, 1, 4);
    sq_v_kernel<<<dim3(8, 8), 1024>>>(1, 2, 5);
    power_v_kernel<<<1, 1024>>>();

    epilogue_kernel<<<(BATCH*CH*NSP)/1024, 256>>>(x, gamma, out);
}

// round 11
// speedup vs baseline: 1.7124x; 1.2706x over previous
#include <cuda_runtime.h>
#include <math.h>
#include <stdint.h>

#define BATCH 4
#define CH    256
#define NSP   4096
#define DQK   32

// ---------------- scratch (__device__ globals: no runtime allocation) -------
__device__ __align__(256) float g_Q[BATCH*NSP*DQK];   // [b][n][d]
__device__ __align__(256) float g_K[BATCH*NSP*DQK];   // [b][n][d]
__device__ __align__(256) float g_V[BATCH*NSP*CH];    // [b][n][e]
__device__ __align__(256) float g_O[BATCH*CH*NSP];    // [b][e][n] (pre-scale)
__device__ __align__(256) float g_G0[CH*CH];
__device__ __align__(256) float g_GA[CH*CH];
__device__ __align__(256) float g_GB[CH*CH];
__device__ float g_tr[16];
__device__ float g_sigma[4];   // [0]=sigma_q [1]=sigma_k [2]=sigma_v

// ---------------- packed f32x2 helpers (Blackwell) --------------------------
__device__ __forceinline__ unsigned long long pk2(float lo, float hi){
    unsigned long long r;
    asm("mov.b64 %0, {%1, %2};" : "=l"(r) : "f"(lo), "f"(hi));
    return r;
}
__device__ __forceinline__ void upk2(unsigned long long a, float& lo, float& hi){
    asm("mov.b64 {%0, %1}, %2;" : "=f"(lo), "=f"(hi) : "l"(a));
}
__device__ __forceinline__ unsigned long long ffma2(unsigned long long a,
                                                    unsigned long long b,
                                                    unsigned long long c){
    unsigned long long d;
    asm("fma.rn.f32x2 %0, %1, %2, %3;" : "=l"(d) : "l"(a), "l"(b), "l"(c));
    return d;
}
__device__ __forceinline__ unsigned long long fmul2(unsigned long long a,
                                                    unsigned long long b){
    unsigned long long d;
    asm("mul.rn.f32x2 %0, %1, %2;" : "=l"(d) : "l"(a), "l"(b));
    return d;
}

// ---------------- cp.async helpers ------------------------------------------
__device__ __forceinline__ void cpa16(const float* dst, const float* src){
    uint32_t d = (uint32_t)__cvta_generic_to_shared(dst);
    asm volatile("cp.async.cg.shared.global [%0], [%1], 16;"
                 :: "r"(d), "l"(src) : "memory");
}
#define CP_COMMIT() asm volatile("cp.async.commit_group;" ::: "memory")
#define CP_WAIT(n)  asm volatile("cp.async.wait_group %0;" :: "n"(n) : "memory")

// ---------------- init ------------------------------------------------------
__global__ void init_kernel(){
    if (threadIdx.x < 16) g_tr[threadIdx.x] = 0.0f;
}

// ---------------- sigma for wq / wk (32x256) --------------------------------
__global__ void sigma_qk_kernel(const float* __restrict__ wq,
                                const float* __restrict__ wk){
    const float* W = (blockIdx.x == 0) ? wq : wk;
    __shared__ float Ws[32][257];
    __shared__ float Ao[32][33];
    __shared__ float Aa[32][33];
    __shared__ float Ab[32][33];
    __shared__ float vsh[32];
    __shared__ float tinv;
    int tid = threadIdx.x;

    for (int m = 0; m < 8; m++){
        int lin = m*1024 + tid;
        Ws[lin >> 8][lin & 255] = W[lin];
    }
    __syncthreads();

    int i = tid >> 5, j = tid & 31;
    float a = 0.f;
    #pragma unroll 8
    for (int c = 0; c < 256; c++) a += Ws[i][c] * Ws[j][c];
    Ao[i][j] = a;
    Aa[i][j] = a;
    __syncthreads();

    for (int s = 0; s < 5; s++){
        float (*cur)[33] = (s & 1) ? Ab : Aa;
        float (*nxt)[33] = (s & 1) ? Aa : Ab;
        if (tid == 0){
            float t = 0.f;
            for (int k2 = 0; k2 < 32; k2++) t += cur[k2][k2];
            tinv = 1.0f / t;
        }
        __syncthreads();
        float acc = 0.f;
        #pragma unroll
        for (int k2 = 0; k2 < 32; k2++) acc += cur[i][k2] * cur[j][k2];
        float ti = tinv;
        nxt[i][j] = acc * ti * ti;
        __syncthreads();
    }

    if (tid < 32){
        vsh[tid] = 1.0f + 0.05f * (float)tid;
        __syncwarp();
        for (int it = 0; it < 40; it++){
            float w = 0.f;
            #pragma unroll
            for (int k2 = 0; k2 < 32; k2++) w += Ab[tid][k2] * vsh[k2];
            float ss = w * w;
            #pragma unroll
            for (int off = 16; off; off >>= 1) ss += __shfl_xor_sync(0xffffffffu, ss, off);
            float sc = rsqrtf(ss);
            __syncwarp();
            vsh[tid] = w * sc;
            __syncwarp();
        }
        float w = 0.f;
        #pragma unroll
        for (int k2 = 0; k2 < 32; k2++) w += Ao[tid][k2] * vsh[k2];
        float num = vsh[tid] * w, den = vsh[tid] * vsh[tid];
        #pragma unroll
        for (int off = 16; off; off >>= 1){
            num += __shfl_xor_sync(0xffffffffu, num, off);
            den += __shfl_xor_sync(0xffffffffu, den, off);
        }
        if (tid == 0) g_sigma[blockIdx.x] = sqrtf(num / den);
    }
}

// ---------------- Gram of wv: G0 = wv wv^T (256x256) ------------------------
__global__ void gram_v_kernel(const float* __restrict__ wv){
    __shared__ float as[32][33], bs[32][33];
    int tid = threadIdx.x;
    int i0 = blockIdx.y * 32, j0 = blockIdx.x * 32;
    int li = tid >> 5, lj = tid & 31;
    float acc = 0.f;
    for (int c0 = 0; c0 < 256; c0 += 32){
        as[li][lj] = wv[(i0 + li)*256 + c0 + lj];
        bs[li][lj] = wv[(j0 + li)*256 + c0 + lj];
        __syncthreads();
        #pragma unroll
        for (int cc = 0; cc < 32; cc++) acc += as[li][cc] * bs[lj][cc];
        __syncthreads();
    }
    g_G0[(i0 + li)*256 + j0 + lj] = acc;
    if (i0 + li == j0 + lj) atomicAdd(&g_tr[0], acc);
}

// ---------------- one trace-normalized squaring of a 256x256 PSD matrix -----
__device__ __forceinline__ float* gbuf(int s){
    return (s == 0) ? g_G0 : ((s == 1) ? g_GA : g_GB);
}
__global__ void sq_v_kernel(int ssel, int dsel, int step){
    const float* src = gbuf(ssel);
    float* dst = gbuf(dsel);
    __shared__ float as[32][33], bs[32][33];
    int tid = threadIdx.x;
    int i0 = blockIdx.y * 32, j0 = blockIdx.x * 32;
    int li = tid >> 5, lj = tid & 31;
    float inv = 1.0f / g_tr[step];
    float acc = 0.f;
    for (int k0 = 0; k0 < 256; k0 += 32){
        as[li][lj] = src[(i0 + li)*256 + k0 + lj];
        bs[li][lj] = src[(j0 + li)*256 + k0 + lj];
        __syncthreads();
        #pragma unroll
        for (int kk = 0; kk < 32; kk++) acc += as[li][kk] * bs[lj][kk];
        __syncthreads();
    }
    acc = acc * inv * inv;
    dst[(i0 + li)*256 + j0 + lj] = acc;
    if (i0 + li == j0 + lj) atomicAdd(&g_tr[step + 1], acc);
}

// ---------------- power + Rayleigh for sigma_v ------------------------------
// 8 applications of (normalized) G^32 -> ~G^256, then Rayleigh on G0.
__global__ void power_v_kernel(){
    __shared__ float vsh[256], vnew[256];
    __shared__ float rss[8], rnum[8], rden[8];
    __shared__ float nscale;
    int tid = threadIdx.x;                // 1024 threads
    int lane = tid & 31, wrp = tid >> 5;
    if (tid < 256) vsh[tid] = 1.0f + 0.013f * (float)tid;
    __syncthreads();

    for (int it = 0; it < 9; it++){
        const float* Mat = (it < 8) ? g_GB : g_G0;
        float part[8] = {0,0,0,0,0,0,0,0};
        #pragma unroll
        for (int m = 0; m < 8; m++){
            int k2 = lane + 32*m;
            float vk = vsh[k2];
            #pragma unroll
            for (int i = 0; i < 8; i++)
                part[i] += Mat[(wrp*8 + i)*256 + k2] * vk;
        }
        #pragma unroll
        for (int i = 0; i < 8; i++){
            float r = part[i];
            #pragma unroll
            for (int off = 16; off; off >>= 1) r += __shfl_down_sync(0xffffffffu, r, off);
            if (lane == 0) vnew[wrp*8 + i] = r;
        }
        __syncthreads();
        if (it < 8){
            if (tid < 256){
                float s2 = vnew[tid] * vnew[tid];
                #pragma unroll
                for (int off = 16; off; off >>= 1) s2 += __shfl_down_sync(0xffffffffu, s2, off);
                if ((tid & 31) == 0) rss[tid >> 5] = s2;
            }
            __syncthreads();
            if (tid == 0){
                float s2 = 0.f;
                for (int u = 0; u < 8; u++) s2 += rss[u];
                nscale = rsqrtf(s2);
            }
            __syncthreads();
            if (tid < 256) vsh[tid] = vnew[tid] * nscale;
            __syncthreads();
        } else {
            if (tid < 256){
                float nv = vsh[tid] * vnew[tid];
                float dv = vsh[tid] * vsh[tid];
                #pragma unroll
                for (int off = 16; off; off >>= 1){
                    nv += __shfl_down_sync(0xffffffffu, nv, off);
                    dv += __shfl_down_sync(0xffffffffu, dv, off);
                }
                if ((tid & 31) == 0){ rnum[tid >> 5] = nv; rden[tid >> 5] = dv; }
            }
            __syncthreads();
            if (tid == 0){
                float n = 0.f, d2 = 0.f;
                for (int u = 0; u < 8; u++){ n += rnum[u]; d2 += rden[u]; }
                g_sigma[2] = sqrtf(n / d2);
            }
        }
    }
}

// ---------------- Q/K projections: out[b][n][d] = sum_c W[d][c] x[b][c][n] --
__global__ void proj_qk_kernel(const float* __restrict__ x,
                               const float* __restrict__ wq,
                               const float* __restrict__ wk){
    const float* W = (blockIdx.z == 0) ? wq : wk;
    float* dst = (blockIdx.z == 0) ? g_Q : g_K;
    int b = blockIdx.y, n0 = blockIdx.x * 64;
    __shared__ float ws[32][33], xs[32][65];
    int tid = threadIdx.x;
    int d = tid & 31, rg = tid >> 5;
    float acc[8] = {0,0,0,0,0,0,0,0};
    const float* xb = x + (size_t)b * CH * NSP;
    for (int c0 = 0; c0 < 256; c0 += 32){
        #pragma unroll
        for (int m = 0; m < 4; m++){
            int lin = m*256 + tid;
            ws[lin >> 5][lin & 31] = W[(lin >> 5)*256 + c0 + (lin & 31)];
        }
        #pragma unroll
        for (int m = 0; m < 8; m++){
            int lin = m*256 + tid;
            int c = lin >> 6, n = lin & 63;
            xs[c][n] = xb[(c0 + c)*NSP + n0 + n];
        }
        __syncthreads();
        #pragma unroll
        for (int cc = 0; cc < 32; cc++){
            float wv_ = ws[d][cc];
            #pragma unroll
            for (int i = 0; i < 8; i++) acc[i] += wv_ * xs[cc][rg*8 + i];
        }
        __syncthreads();
    }
    #pragma unroll
    for (int i = 0; i < 8; i++)
        dst[(size_t)b*NSP*DQK + (size_t)(n0 + rg*8 + i)*DQK + d] = acc[i];
}

// ---------------- V projection: g_V[b][n][e] = sum_c wv[e][c] x[b][c][n] ----
__global__ void proj_v_kernel(const float* __restrict__ x,
                              const float* __restrict__ wv){
    int b = blockIdx.z, e0 = blockIdx.y * 64, n0 = blockIdx.x * 64;
    __shared__ float ws[64][33], xs[32][65];
    int tid = threadIdx.x;
    int ex = tid & 15, ny = tid >> 4;
    float acc[4][4] = {};
    const float* xb = x + (size_t)b * CH * NSP;
    for (int c0 = 0; c0 < 256; c0 += 32){
        #pragma unroll
        for (int m = 0; m < 8; m++){
            int lin = m*256 + tid;
            ws[lin >> 5][lin & 31] = wv[(e0 + (lin >> 5))*256 + c0 + (lin & 31)];
        }
        #pragma unroll
        for (int m = 0; m < 8; m++){
            int lin = m*256 + tid;
            int c = lin >> 6, n = lin & 63;
            xs[c][n] = xb[(c0 + c)*NSP + n0 + n];
        }
        __syncthreads();
        #pragma unroll
        for (int cc = 0; cc < 32; cc++){
            float er[4], xr[4];
            #pragma unroll
            for (int jc = 0; jc < 4; jc++) er[jc] = ws[ex*4 + jc][cc];
            #pragma unroll
            for (int i = 0; i < 4; i++) xr[i] = xs[cc][ny*4 + i];
            #pragma unroll
            for (int i = 0; i < 4; i++)
                #pragma unroll
                for (int jc = 0; jc < 4; jc++)
                    acc[i][jc] += xr[i] * er[jc];
        }
        __syncthreads();
    }
    #pragma unroll
    for (int i = 0; i < 4; i++){
        float4 o = make_float4(acc[i][0], acc[i][1], acc[i][2], acc[i][3]);
        *(float4*)&g_V[(size_t)b*NSP*CH + (size_t)(n0 + ny*4 + i)*CH + e0 + ex*4] = o;
    }
}

// ---------------- flash attention (writes O/l to g_O) -----------------------
// Dynamic smem layout (floats):
//   Qs  @ 0      [64][36]       (2304)
//   Ks  @ 2304   [2][64][36]    (4608)
//   Pt  @ 6912   [64 key][68]   (4352)  Pt[k][q] = P[q][k]  (transposed)
//   Vsm @ 11264  [4][16][256]   (16384) 4 independent chunk buffers
//   mrow@ 27648, lrow@ 27712, arow@ 27776  -> total 27840 floats = 111360 B
#define FLASH_SMEM 111360

__global__ void __launch_bounds__(256, 2)
flash_kernel(float* __restrict__ Og){
    extern __shared__ float sm[];
    float* Qs   = sm;
    float* Ks   = sm + 2304;
    float* Pt   = sm + 6912;
    float* Vsm  = sm + 11264;
    float* mrow = sm + 27648;
    float* lrow = sm + 27712;
    float* arow = sm + 27776;

    int tid = threadIdx.x;
    int b = blockIdx.y, i0 = blockIdx.x * 64;
    int tx = tid & 31, ty = tid >> 5;
    int rid = tid >> 4, cid = tid & 15;   // rid: key groups, cid: query groups

    const float* Qg  = g_Q + (size_t)b*NSP*DQK + (size_t)i0*DQK;
    const float* Kgb = g_K + (size_t)b*NSP*DQK;
    const float* Vgb = g_V + (size_t)b*NSP*CH;

    float lscale = 1.0f / (g_sigma[0] * g_sigma[1] * sqrtf((float)DQK));

    // load Q tile (plain loads, once)
    #pragma unroll
    for (int i = 0; i < 2; i++){
        int f = i*256 + tid;
        int r = f >> 3, q = f & 7;
        float4 v = *(const float4*)(Qg + r*32 + q*4);
        *(float4*)(Qs + r*36 + q*4) = v;
    }
    if (tid < 64){ mrow[tid] = -INFINITY; lrow[tid] = 0.f; }

    unsigned long long acc[8][4];
    #pragma unroll
    for (int ii = 0; ii < 8; ii++)
        #pragma unroll
        for (int k2 = 0; k2 < 4; k2++) acc[ii][k2] = 0ull;

    // prefetch K tile 0
    #pragma unroll
    for (int i = 0; i < 2; i++){
        int f = i*256 + tid;
        int r = f >> 3, q = f & 7;
        cpa16(Ks + r*36 + q*4, Kgb + (size_t)r*DQK + q*4);
    }
    CP_COMMIT();

    for (int jt = 0; jt < 64; jt++){
        int kb = jt & 1;
        int j0 = jt * 64;

        // issue ALL 4 V chunks into 4 independent buffers
        #pragma unroll
        for (int c = 0; c < 4; c++){
            #pragma unroll
            for (int i = 0; i < 4; i++){
                int f = i*256 + tid;
                int r = f >> 6, q = f & 63;          // r in [0,16), q in [0,64)
                cpa16(Vsm + c*4096 + r*256 + q*4,
                      Vgb + (size_t)(j0 + c*16 + r)*CH + q*4);
            }
            CP_COMMIT();
        }

        CP_WAIT(4);          // K(jt) done (oldest of 5 pending groups)
        __syncthreads();     // [1] Ks visible

        // S = Q K^T * lscale -> Pt[key][query]  (thread: 4 keys x 4 queries)
        {
            const float* Kb = Ks + kb*2304;
            float s[4][4] = {};   // [a=key][b=query]
            #pragma unroll
            for (int d4 = 0; d4 < 8; d4++){
                float4 k4[4], q4[4];
                #pragma unroll
                for (int a = 0; a < 4; a++)
                    k4[a] = *(const float4*)(Kb + (rid*4 + a)*36 + d4*4);
                #pragma unroll
                for (int bq = 0; bq < 4; bq++)
                    q4[bq] = *(const float4*)(Qs + (cid*4 + bq)*36 + d4*4);
                #pragma unroll
                for (int a = 0; a < 4; a++)
                    #pragma unroll
                    for (int bq = 0; bq < 4; bq++){
                        s[a][bq] += k4[a].x * q4[bq].x + k4[a].y * q4[bq].y
                                  + k4[a].z * q4[bq].z + k4[a].w * q4[bq].w;
                    }
            }
            #pragma unroll
            for (int a = 0; a < 4; a++){
                float4 row = make_float4(s[a][0]*lscale, s[a][1]*lscale,
                                         s[a][2]*lscale, s[a][3]*lscale);
                *(float4*)(Pt + (rid*4 + a)*68 + cid*4) = row;
            }
        }

        // prefetch next K tile (wraps harmlessly at jt=63)
        {
            int nj = ((jt + 1) & 63) * 64;
            #pragma unroll
            for (int i = 0; i < 2; i++){
                int f = i*256 + tid;
                int r = f >> 3, q = f & 7;
                cpa16(Ks + (kb ^ 1)*2304 + r*36 + q*4,
                      Kgb + (size_t)(nj + r)*DQK + q*4);
            }
            CP_COMMIT();
        }
        __syncthreads();     // [2] raw S complete in Pt

        // streaming softmax (4 threads per query row; keys strided by 4)
        {
            int r = tid >> 2, g = tid & 3;
            float mx = -INFINITY;
            #pragma unroll
            for (int c = 0; c < 16; c++)
                mx = fmaxf(mx, Pt[(4*c + g)*68 + r]);
            mx = fmaxf(mx, __shfl_xor_sync(0xffffffffu, mx, 1));
            mx = fmaxf(mx, __shfl_xor_sync(0xffffffffu, mx, 2));
            float mold = mrow[r];
            float mnew = fmaxf(mold, mx);
            float sum = 0.f;
            #pragma unroll
            for (int c = 0; c < 16; c++){
                float p = __expf(Pt[(4*c + g)*68 + r] - mnew);
                Pt[(4*c + g)*68 + r] = p;
                sum += p;
            }
            sum += __shfl_xor_sync(0xffffffffu, sum, 1);
            sum += __shfl_xor_sync(0xffffffffu, sum, 2);
            if (g == 0){
                float al = __expf(mold - mnew);
                lrow[r] = lrow[r] * al + sum;
                mrow[r] = mnew;
                arow[r] = al;
            }
        }

        CP_WAIT(0);          // ALL V chunks (+Knext) arrived
        __syncthreads();     // [3] exp(P) + all V visible

        // rescale accumulator (skip when all alphas are exactly 1)
        {
            float al8[8]; bool allone = true;
            #pragma unroll
            for (int ii = 0; ii < 8; ii++){
                al8[ii] = arow[ty*8 + ii];
                allone = allone && (al8[ii] == 1.0f);
            }
            if (!allone){
                #pragma unroll
                for (int ii = 0; ii < 8; ii++){
                    unsigned long long a2 = pk2(al8[ii], al8[ii]);
                    #pragma unroll
                    for (int k2 = 0; k2 < 4; k2++)
                        acc[ii][k2] = fmul2(acc[ii][k2], a2);
                }
            }
        }

        // PV: 64 keys, straight-line, barrier-free
        #pragma unroll
        for (int c = 0; c < 4; c++){
            const float* Vb = Vsm + c*4096;
            #pragma unroll 4
            for (int jj = 0; jj < 16; jj++){
                int key = c*16 + jj;
                // P for this warp's 8 queries: 2 broadcast LDS.128
                float4 pa = *(const float4*)(Pt + key*68 + ty*8);
                float4 pb = *(const float4*)(Pt + key*68 + ty*8 + 4);
                unsigned long long p2[8];
                p2[0] = pk2(pa.x, pa.x); p2[1] = pk2(pa.y, pa.y);
                p2[2] = pk2(pa.z, pa.z); p2[3] = pk2(pa.w, pa.w);
                p2[4] = pk2(pb.x, pb.x); p2[5] = pk2(pb.y, pb.y);
                p2[6] = pk2(pb.z, pb.z); p2[7] = pk2(pb.w, pb.w);
                // V: channels {4tx..4tx+3} and {128+4tx..+3} = 2 LDS.128
                const ulonglong2* va  = (const ulonglong2*)(Vb + jj*256 + 4*tx);
                const ulonglong2* vbp = (const ulonglong2*)(Vb + jj*256 + 128 + 4*tx);
                ulonglong2 v01 = *va;
                ulonglong2 v23 = *vbp;
                #pragma unroll
                for (int ii = 0; ii < 8; ii++){
                    acc[ii][0] = ffma2(v01.x, p2[ii], acc[ii][0]);
                    acc[ii][1] = ffma2(v01.y, p2[ii], acc[ii][1]);
                    acc[ii][2] = ffma2(v23.x, p2[ii], acc[ii][2]);
                    acc[ii][3] = ffma2(v23.y, p2[ii], acc[ii][3]);
                }
            }
        }
        __syncthreads();   // [4] all warps done with Pt/Vsm before next tile
    }

    // epilogue: write O/l to g_O[b][e][n]
    float linv[8];
    #pragma unroll
    for (int ii = 0; ii < 8; ii++) linv[ii] = 1.0f / lrow[ty*8 + ii];

    size_t base_n = (size_t)i0 + ty*8;
    #pragma unroll
    for (int k2 = 0; k2 < 4; k2++){
        float lo[8], hi[8];
        #pragma unroll
        for (int ii = 0; ii < 8; ii++) upk2(acc[ii][k2], lo[ii], hi[ii]);
        // acc[.][0]={4tx,4tx+1} [1]={4tx+2,4tx+3} [2]={128+4tx,..} [3]={128+4tx+2,..}
        int e_base = (k2 >> 1)*128 + 4*tx + (k2 & 1)*2;
        #pragma unroll
        for (int h = 0; h < 2; h++){
            int e = e_base + h;
            size_t idx = (size_t)b*CH*NSP + (size_t)e*NSP + base_n;
            float vals[8];
            #pragma unroll
            for (int ii = 0; ii < 8; ii++)
                vals[ii] = (h ? hi[ii] : lo[ii]) * linv[ii];
            float4 o0 = make_float4(vals[0], vals[1], vals[2], vals[3]);
            float4 o1 = make_float4(vals[4], vals[5], vals[6], vals[7]);
            *(float4*)&Og[idx]     = o0;
            *(float4*)&Og[idx + 4] = o1;
        }
    }
}

// ---------------- epilogue: out = x + (gamma/sigma_v) * O -------------------
__global__ void epilogue_kernel(const float* __restrict__ x,
                                const float* __restrict__ gamma,
                                float* __restrict__ out){
    size_t i = ((size_t)blockIdx.x * 256 + threadIdx.x) * 4;
    float s = gamma[0] / g_sigma[2];
    float4 xv = *(const float4*)&x[i];
    float4 ov = *(const float4*)&g_O[i];
    float4 r = make_float4(xv.x + s*ov.x, xv.y + s*ov.y,
                           xv.z + s*ov.z, xv.w + s*ov.w);
    *(float4*)&out[i] = r;
}

// ---------------- launch ----------------------------------------------------
extern "C" void kernel_launch(void* const* d_in, const int* in_sizes, int n_in,
                              void* d_out, int out_size){
    (void)in_sizes; (void)n_in; (void)out_size;
    const float* x     = (const float*)d_in[0];
    const float* wq    = (const float*)d_in[1];
    const float* wk    = (const float*)d_in[2];
    const float* wv    = (const float*)d_in[3];
    const float* gamma = (const float*)d_in[4];
    float* out = (float*)d_out;

    cudaFuncSetAttribute(flash_kernel,
                         cudaFuncAttributeMaxDynamicSharedMemorySize, FLASH_SMEM);

    float* Og;
    cudaGetSymbolAddress((void**)&Og, g_O);

    init_kernel<<<1, 32>>>();
    sigma_qk_kernel<<<2, 1024>>>(wq, wk);
    proj_qk_kernel<<<dim3(NSP/64, BATCH, 2), 256>>>(x, wq, wk);
    proj_v_kernel<<<dim3(NSP/64, CH/64, BATCH), 256>>>(x, wv);
    gram_v_kernel<<<dim3(8, 8), 1024>>>(wv);
    flash_kernel<<<dim3(NSP/64, BATCH), 256, FLASH_SMEM>>>(Og);

    // sigma_v chain (independent of flash): 5 squarings -> G^32 in g_GB
    sq_v_kernel<<<dim3(8, 8), 1024>>>(0, 1, 0);
    sq_v_kernel<<<dim3(8, 8), 1024>>>(1, 2, 1);
    sq_v_kernel<<<dim3(8, 8), 1024>>>(2, 1, 2);
    sq_v_kernel<<<dim3(8, 8), 1024>>>(1, 2, 3);
    sq_v_kernel<<<dim3(8, 8), 1024>>>(2, 1, 4);
    power_v_kernel<<<1, 1024>>>();

    epilogue_kernel<<<(BATCH*CH*NSP)/1024, 256>>>(x, gamma, out);
}

// round 12
// speedup vs baseline: 2.1018x; 1.2274x over previous
#include <cuda_runtime.h>
#include <math.h>
#include <stdint.h>

#define BATCH 4
#define CH    256
#define NSP   4096
#define DQK   32

// ---------------- scratch (__device__ globals: no runtime allocation) -------
__device__ __align__(256) float g_Q[BATCH*DQK*NSP];   // [b][d][n]  (TRANSPOSED)
__device__ __align__(256) float g_K[BATCH*DQK*NSP];   // [b][d][n]  (TRANSPOSED)
__device__ __align__(256) float g_V[BATCH*NSP*CH];    // [b][n][e]
__device__ __align__(256) float g_O[BATCH*CH*NSP];    // [b][e][n] (pre-scale)
__device__ __align__(256) float g_G0[CH*CH];
__device__ __align__(256) float g_GA[CH*CH];
__device__ __align__(256) float g_GB[CH*CH];
__device__ float g_tr[16];
__device__ float g_sigma[4];   // [0]=sigma_q [1]=sigma_k [2]=sigma_v

// ---------------- packed f32x2 helpers (Blackwell) --------------------------
__device__ __forceinline__ unsigned long long pk2(float lo, float hi){
    unsigned long long r;
    asm("mov.b64 %0, {%1, %2};" : "=l"(r) : "f"(lo), "f"(hi));
    return r;
}
__device__ __forceinline__ void upk2(unsigned long long a, float& lo, float& hi){
    asm("mov.b64 {%0, %1}, %2;" : "=f"(lo), "=f"(hi) : "l"(a));
}
__device__ __forceinline__ unsigned long long ffma2(unsigned long long a,
                                                    unsigned long long b,
                                                    unsigned long long c){
    unsigned long long d;
    asm("fma.rn.f32x2 %0, %1, %2, %3;" : "=l"(d) : "l"(a), "l"(b), "l"(c));
    return d;
}
__device__ __forceinline__ unsigned long long fmul2(unsigned long long a,
                                                    unsigned long long b){
    unsigned long long d;
    asm("mul.rn.f32x2 %0, %1, %2;" : "=l"(d) : "l"(a), "l"(b));
    return d;
}

// ---------------- cp.async helpers ------------------------------------------
__device__ __forceinline__ void cpa16(const float* dst, const float* src){
    uint32_t d = (uint32_t)__cvta_generic_to_shared(dst);
    asm volatile("cp.async.cg.shared.global [%0], [%1], 16;"
                 :: "r"(d), "l"(src) : "memory");
}
#define CP_COMMIT() asm volatile("cp.async.commit_group;" ::: "memory")
#define CP_WAIT(n)  asm volatile("cp.async.wait_group %0;" :: "n"(n) : "memory")

// ---------------- init ------------------------------------------------------
__global__ void init_kernel(){
    if (threadIdx.x < 16) g_tr[threadIdx.x] = 0.0f;
}

// ---------------- sigma for wq / wk (32x256) --------------------------------
__global__ void sigma_qk_kernel(const float* __restrict__ wq,
                                const float* __restrict__ wk){
    const float* W = (blockIdx.x == 0) ? wq : wk;
    __shared__ float Ws[32][257];
    __shared__ float Ao[32][33];
    __shared__ float Aa[32][33];
    __shared__ float Ab[32][33];
    __shared__ float vsh[32];
    __shared__ float tinv;
    int tid = threadIdx.x;

    for (int m = 0; m < 8; m++){
        int lin = m*1024 + tid;
        Ws[lin >> 8][lin & 255] = W[lin];
    }
    __syncthreads();

    int i = tid >> 5, j = tid & 31;
    float a = 0.f;
    #pragma unroll 8
    for (int c = 0; c < 256; c++) a += Ws[i][c] * Ws[j][c];
    Ao[i][j] = a;
    Aa[i][j] = a;
    __syncthreads();

    for (int s = 0; s < 5; s++){
        float (*cur)[33] = (s & 1) ? Ab : Aa;
        float (*nxt)[33] = (s & 1) ? Aa : Ab;
        if (tid == 0){
            float t = 0.f;
            for (int k2 = 0; k2 < 32; k2++) t += cur[k2][k2];
            tinv = 1.0f / t;
        }
        __syncthreads();
        float acc = 0.f;
        #pragma unroll
        for (int k2 = 0; k2 < 32; k2++) acc += cur[i][k2] * cur[j][k2];
        float ti = tinv;
        nxt[i][j] = acc * ti * ti;
        __syncthreads();
    }

    if (tid < 32){
        vsh[tid] = 1.0f + 0.05f * (float)tid;
        __syncwarp();
        for (int it = 0; it < 40; it++){
            float w = 0.f;
            #pragma unroll
            for (int k2 = 0; k2 < 32; k2++) w += Ab[tid][k2] * vsh[k2];
            float ss = w * w;
            #pragma unroll
            for (int off = 16; off; off >>= 1) ss += __shfl_xor_sync(0xffffffffu, ss, off);
            float sc = rsqrtf(ss);
            __syncwarp();
            vsh[tid] = w * sc;
            __syncwarp();
        }
        float w = 0.f;
        #pragma unroll
        for (int k2 = 0; k2 < 32; k2++) w += Ao[tid][k2] * vsh[k2];
        float num = vsh[tid] * w, den = vsh[tid] * vsh[tid];
        #pragma unroll
        for (int off = 16; off; off >>= 1){
            num += __shfl_xor_sync(0xffffffffu, num, off);
            den += __shfl_xor_sync(0xffffffffu, den, off);
        }
        if (tid == 0) g_sigma[blockIdx.x] = sqrtf(num / den);
    }
}

// ---------------- Gram of wv: G0 = wv wv^T (256x256) ------------------------
__global__ void gram_v_kernel(const float* __restrict__ wv){
    __shared__ float as[32][33], bs[32][33];
    int tid = threadIdx.x;
    int i0 = blockIdx.y * 32, j0 = blockIdx.x * 32;
    int li = tid >> 5, lj = tid & 31;
    float acc = 0.f;
    for (int c0 = 0; c0 < 256; c0 += 32){
        as[li][lj] = wv[(i0 + li)*256 + c0 + lj];
        bs[li][lj] = wv[(j0 + li)*256 + c0 + lj];
        __syncthreads();
        #pragma unroll
        for (int cc = 0; cc < 32; cc++) acc += as[li][cc] * bs[lj][cc];
        __syncthreads();
    }
    g_G0[(i0 + li)*256 + j0 + lj] = acc;
    if (i0 + li == j0 + lj) atomicAdd(&g_tr[0], acc);
}

// ---------------- one trace-normalized squaring of a 256x256 PSD matrix -----
__device__ __forceinline__ float* gbuf(int s){
    return (s == 0) ? g_G0 : ((s == 1) ? g_GA : g_GB);
}
__global__ void sq_v_kernel(int ssel, int dsel, int step){
    const float* src = gbuf(ssel);
    float* dst = gbuf(dsel);
    __shared__ float as[32][33], bs[32][33];
    int tid = threadIdx.x;
    int i0 = blockIdx.y * 32, j0 = blockIdx.x * 32;
    int li = tid >> 5, lj = tid & 31;
    float inv = 1.0f / g_tr[step];
    float acc = 0.f;
    for (int k0 = 0; k0 < 256; k0 += 32){
        as[li][lj] = src[(i0 + li)*256 + k0 + lj];
        bs[li][lj] = src[(j0 + li)*256 + k0 + lj];
        __syncthreads();
        #pragma unroll
        for (int kk = 0; kk < 32; kk++) acc += as[li][kk] * bs[lj][kk];
        __syncthreads();
    }
    acc = acc * inv * inv;
    dst[(i0 + li)*256 + j0 + lj] = acc;
    if (i0 + li == j0 + lj) atomicAdd(&g_tr[step + 1], acc);
}

// ---------------- power + Rayleigh for sigma_v ------------------------------
__global__ void power_v_kernel(){
    __shared__ float vsh[256], vnew[256];
    __shared__ float rss[8], rnum[8], rden[8];
    __shared__ float nscale;
    int tid = threadIdx.x;                // 1024 threads
    int lane = tid & 31, wrp = tid >> 5;
    if (tid < 256) vsh[tid] = 1.0f + 0.013f * (float)tid;
    __syncthreads();

    for (int it = 0; it < 9; it++){
        const float* Mat = (it < 8) ? g_GB : g_G0;
        float part[8] = {0,0,0,0,0,0,0,0};
        #pragma unroll
        for (int m = 0; m < 8; m++){
            int k2 = lane + 32*m;
            float vk = vsh[k2];
            #pragma unroll
            for (int i = 0; i < 8; i++)
                part[i] += Mat[(wrp*8 + i)*256 + k2] * vk;
        }
        #pragma unroll
        for (int i = 0; i < 8; i++){
            float r = part[i];
            #pragma unroll
            for (int off = 16; off; off >>= 1) r += __shfl_down_sync(0xffffffffu, r, off);
            if (lane == 0) vnew[wrp*8 + i] = r;
        }
        __syncthreads();
        if (it < 8){
            if (tid < 256){
                float s2 = vnew[tid] * vnew[tid];
                #pragma unroll
                for (int off = 16; off; off >>= 1) s2 += __shfl_down_sync(0xffffffffu, s2, off);
                if ((tid & 31) == 0) rss[tid >> 5] = s2;
            }
            __syncthreads();
            if (tid == 0){
                float s2 = 0.f;
                for (int u = 0; u < 8; u++) s2 += rss[u];
                nscale = rsqrtf(s2);
            }
            __syncthreads();
            if (tid < 256) vsh[tid] = vnew[tid] * nscale;
            __syncthreads();
        } else {
            if (tid < 256){
                float nv = vsh[tid] * vnew[tid];
                float dv = vsh[tid] * vsh[tid];
                #pragma unroll
                for (int off = 16; off; off >>= 1){
                    nv += __shfl_down_sync(0xffffffffu, nv, off);
                    dv += __shfl_down_sync(0xffffffffu, dv, off);
                }
                if ((tid & 31) == 0){ rnum[tid >> 5] = nv; rden[tid >> 5] = dv; }
            }
            __syncthreads();
            if (tid == 0){
                float n = 0.f, d2 = 0.f;
                for (int u = 0; u < 8; u++){ n += rnum[u]; d2 += rden[u]; }
                g_sigma[2] = sqrtf(n / d2);
            }
        }
    }
}

// ---------------- merged projections ----------------------------------------
// z = 0: Q -> g_Q[b][d][n] (transposed)   z = 1: K -> g_K[b][d][n]
// z = 2..5: V -> g_V[b][n][e], e0 = (z-2)*64
__global__ void proj_all_kernel(const float* __restrict__ x,
                                const float* __restrict__ wq,
                                const float* __restrict__ wk,
                                const float* __restrict__ wv){
    int z = blockIdx.z;
    int b = blockIdx.y, n0 = blockIdx.x * 64;
    int tid = threadIdx.x;
    const float* xb = x + (size_t)b * CH * NSP;

    if (z < 2){
        // ---- Q/K projection, transposed output [d][n] ----
        const float* W = (z == 0) ? wq : wk;
        float* dst = ((z == 0) ? g_Q : g_K) + (size_t)b*DQK*NSP;
        __shared__ float ws[32][33], xs[32][65];
        int n = tid & 63, dg = tid >> 6;          // d = dg*8 + i
        float acc[8] = {0,0,0,0,0,0,0,0};
        for (int c0 = 0; c0 < 256; c0 += 32){
            #pragma unroll
            for (int m = 0; m < 4; m++){
                int lin = m*256 + tid;
                ws[lin >> 5][lin & 31] = W[(lin >> 5)*256 + c0 + (lin & 31)];
            }
            #pragma unroll
            for (int m = 0; m < 8; m++){
                int lin = m*256 + tid;
                int c = lin >> 6, nn = lin & 63;
                xs[c][nn] = xb[(c0 + c)*NSP + n0 + nn];
            }
            __syncthreads();
            #pragma unroll
            for (int cc = 0; cc < 32; cc++){
                float xv = xs[cc][n];
                #pragma unroll
                for (int i = 0; i < 8; i++)
                    acc[i] += ws[dg*8 + i][cc] * xv;
            }
            __syncthreads();
        }
        #pragma unroll
        for (int i = 0; i < 8; i++)
            dst[(size_t)(dg*8 + i)*NSP + n0 + n] = acc[i];
    } else {
        // ---- V projection: g_V[b][n][e] ----
        int e0 = (z - 2) * 64;
        __shared__ float ws[64][33], xs[32][65];
        int ex = tid & 15, ny = tid >> 4;
        float acc[4][4] = {};
        for (int c0 = 0; c0 < 256; c0 += 32){
            #pragma unroll
            for (int m = 0; m < 8; m++){
                int lin = m*256 + tid;
                ws[lin >> 5][lin & 31] = wv[(e0 + (lin >> 5))*256 + c0 + (lin & 31)];
            }
            #pragma unroll
            for (int m = 0; m < 8; m++){
                int lin = m*256 + tid;
                int c = lin >> 6, nn = lin & 63;
                xs[c][nn] = xb[(c0 + c)*NSP + n0 + nn];
            }
            __syncthreads();
            #pragma unroll
            for (int cc = 0; cc < 32; cc++){
                float er[4], xr[4];
                #pragma unroll
                for (int jc = 0; jc < 4; jc++) er[jc] = ws[ex*4 + jc][cc];
                #pragma unroll
                for (int i = 0; i < 4; i++) xr[i] = xs[cc][ny*4 + i];
                #pragma unroll
                for (int i = 0; i < 4; i++)
                    #pragma unroll
                    for (int jc = 0; jc < 4; jc++)
                        acc[i][jc] += xr[i] * er[jc];
            }
            __syncthreads();
        }
        #pragma unroll
        for (int i = 0; i < 4; i++){
            float4 o = make_float4(acc[i][0], acc[i][1], acc[i][2], acc[i][3]);
            *(float4*)&g_V[(size_t)b*NSP*CH + (size_t)(n0 + ny*4 + i)*CH + e0 + ex*4] = o;
        }
    }
}

// ---------------- flash attention (writes O/l to g_O) -----------------------
// Dynamic smem layout (floats):
//   Qs  @ 0      [32 d][68]     (2176)  Q transposed: Qs[d][query]
//   Ks  @ 2176   [2][32 d][68]  (4352)  K transposed: Ks[d][key]
//   Pt  @ 6528   [64 key][68]   (4352)  Pt[k][q] = P[q][k]
//   Vsm @ 10880  [4][16][256]   (16384) 4 independent chunk buffers
//   mrow@ 27264, lrow@ 27328, arow@ 27392 -> total 27456 floats = 109824 B
#define FLASH_SMEM 109824

__global__ void __launch_bounds__(256, 2)
flash_kernel(float* __restrict__ Og){
    extern __shared__ float sm[];
    float* Qs   = sm;
    float* Ks   = sm + 2176;
    float* Pt   = sm + 6528;
    float* Vsm  = sm + 10880;
    float* mrow = sm + 27264;
    float* lrow = sm + 27328;
    float* arow = sm + 27392;

    int tid = threadIdx.x;
    int b = blockIdx.y, i0 = blockIdx.x * 64;
    int tx = tid & 31, ty = tid >> 5;
    int rid = tid >> 4, cid = tid & 15;   // rid: key group (x4), cid: query group (x4)

    const float* Qg  = g_Q + (size_t)b*DQK*NSP;   // [d][n]
    const float* Kgb = g_K + (size_t)b*DQK*NSP;   // [d][n]
    const float* Vgb = g_V + (size_t)b*NSP*CH;    // [n][e]

    float lscale = 1.0f / (g_sigma[0] * g_sigma[1] * sqrtf((float)DQK));

    // load Q tile transposed: Qs[d][0..63] = Q[d][i0..i0+63]
    #pragma unroll
    for (int m = 0; m < 2; m++){
        int f = m*256 + tid;
        int d = f >> 4, u = f & 15;
        float4 v = *(const float4*)(Qg + (size_t)d*NSP + i0 + u*4);
        *(float4*)(Qs + d*68 + u*4) = v;
    }
    if (tid < 64){ mrow[tid] = -INFINITY; lrow[tid] = 0.f; }

    unsigned long long acc[8][4];
    #pragma unroll
    for (int ii = 0; ii < 8; ii++)
        #pragma unroll
        for (int k2 = 0; k2 < 4; k2++) acc[ii][k2] = 0ull;

    // prefetch K tile 0 (transposed rows)
    #pragma unroll
    for (int m = 0; m < 2; m++){
        int f = m*256 + tid;
        int d = f >> 4, u = f & 15;
        cpa16(Ks + d*68 + u*4, Kgb + (size_t)d*NSP + u*4);
    }
    CP_COMMIT();

    for (int jt = 0; jt < 64; jt++){
        int kb = jt & 1;
        int j0 = jt * 64;

        // issue ALL 4 V chunks into 4 independent buffers
        #pragma unroll
        for (int c = 0; c < 4; c++){
            #pragma unroll
            for (int i = 0; i < 4; i++){
                int f = i*256 + tid;
                int r = f >> 6, q = f & 63;
                cpa16(Vsm + c*4096 + r*256 + q*4,
                      Vgb + (size_t)(j0 + c*16 + r)*CH + q*4);
            }
            CP_COMMIT();
        }

        CP_WAIT(4);          // K(jt) arrived (oldest pending)
        __syncthreads();     // [1] Ks visible to all warps

        // S = K^T Q * lscale -> Pt[key][query]; conflict-free row reads
        {
            const float* Kb = Ks + kb*2176;
            float s[4][4] = {};   // [a=key][bq=query]
            #pragma unroll
            for (int d = 0; d < 32; d++){
                float4 k4 = *(const float4*)(Kb + d*68 + rid*4);
                float4 q4 = *(const float4*)(Qs + d*68 + cid*4);
                s[0][0] += k4.x*q4.x; s[0][1] += k4.x*q4.y;
                s[0][2] += k4.x*q4.z; s[0][3] += k4.x*q4.w;
                s[1][0] += k4.y*q4.x; s[1][1] += k4.y*q4.y;
                s[1][2] += k4.y*q4.z; s[1][3] += k4.y*q4.w;
                s[2][0] += k4.z*q4.x; s[2][1] += k4.z*q4.y;
                s[2][2] += k4.z*q4.z; s[2][3] += k4.z*q4.w;
                s[3][0] += k4.w*q4.x; s[3][1] += k4.w*q4.y;
                s[3][2] += k4.w*q4.z; s[3][3] += k4.w*q4.w;
            }
            #pragma unroll
            for (int a = 0; a < 4; a++){
                float4 row = make_float4(s[a][0]*lscale, s[a][1]*lscale,
                                         s[a][2]*lscale, s[a][3]*lscale);
                *(float4*)(Pt + (rid*4 + a)*68 + cid*4) = row;
            }
        }

        // prefetch next K tile (wraps harmlessly at jt=63)
        {
            int nj = ((jt + 1) & 63) * 64;
            #pragma unroll
            for (int m = 0; m < 2; m++){
                int f = m*256 + tid;
                int d = f >> 4, u = f & 15;
                cpa16(Ks + (kb ^ 1)*2176 + d*68 + u*4,
                      Kgb + (size_t)d*NSP + nj + u*4);
            }
            CP_COMMIT();
        }
        __syncthreads();     // [2] raw S complete in Pt

        // streaming softmax (4 threads per query row; keys strided by 4)
        {
            int r = tid >> 2, g = tid & 3;
            float mx = -INFINITY;
            #pragma unroll
            for (int c = 0; c < 16; c++)
                mx = fmaxf(mx, Pt[(4*c + g)*68 + r]);
            mx = fmaxf(mx, __shfl_xor_sync(0xffffffffu, mx, 1));
            mx = fmaxf(mx, __shfl_xor_sync(0xffffffffu, mx, 2));
            float mold = mrow[r];
            float mnew = fmaxf(mold, mx);
            float sum = 0.f;
            #pragma unroll
            for (int c = 0; c < 16; c++){
                float p = __expf(Pt[(4*c + g)*68 + r] - mnew);
                Pt[(4*c + g)*68 + r] = p;
                sum += p;
            }
            sum += __shfl_xor_sync(0xffffffffu, sum, 1);
            sum += __shfl_xor_sync(0xffffffffu, sum, 2);
            if (g == 0){
                float al = __expf(mold - mnew);
                lrow[r] = lrow[r] * al + sum;
                mrow[r] = mnew;
                arow[r] = al;
            }
        }

        CP_WAIT(1);          // all 4 V chunks arrived (next-K may still pend)
        __syncthreads();     // [3] exp(P) + all V visible

        // rescale accumulator (skip when all alphas are exactly 1)
        {
            float al8[8]; bool allone = true;
            #pragma unroll
            for (int ii = 0; ii < 8; ii++){
                al8[ii] = arow[ty*8 + ii];
                allone = allone && (al8[ii] == 1.0f);
            }
            if (!allone){
                #pragma unroll
                for (int ii = 0; ii < 8; ii++){
                    unsigned long long a2 = pk2(al8[ii], al8[ii]);
                    #pragma unroll
                    for (int k2 = 0; k2 < 4; k2++)
                        acc[ii][k2] = fmul2(acc[ii][k2], a2);
                }
            }
        }

        // PV: 64 keys, straight-line, barrier-free
        #pragma unroll
        for (int c = 0; c < 4; c++){
            const float* Vb = Vsm + c*4096;
            #pragma unroll 4
            for (int jj = 0; jj < 16; jj++){
                int key = c*16 + jj;
                float4 pa = *(const float4*)(Pt + key*68 + ty*8);
                float4 pb = *(const float4*)(Pt + key*68 + ty*8 + 4);
                unsigned long long p2[8];
                p2[0] = pk2(pa.x, pa.x); p2[1] = pk2(pa.y, pa.y);
                p2[2] = pk2(pa.z, pa.z); p2[3] = pk2(pa.w, pa.w);
                p2[4] = pk2(pb.x, pb.x); p2[5] = pk2(pb.y, pb.y);
                p2[6] = pk2(pb.z, pb.z); p2[7] = pk2(pb.w, pb.w);
                const ulonglong2* va  = (const ulonglong2*)(Vb + jj*256 + 4*tx);
                const ulonglong2* vbp = (const ulonglong2*)(Vb + jj*256 + 128 + 4*tx);
                ulonglong2 v01 = *va;
                ulonglong2 v23 = *vbp;
                #pragma unroll
                for (int ii = 0; ii < 8; ii++){
                    acc[ii][0] = ffma2(v01.x, p2[ii], acc[ii][0]);
                    acc[ii][1] = ffma2(v01.y, p2[ii], acc[ii][1]);
                    acc[ii][2] = ffma2(v23.x, p2[ii], acc[ii][2]);
                    acc[ii][3] = ffma2(v23.y, p2[ii], acc[ii][3]);
                }
            }
        }
        __syncthreads();   // [4] all warps done with Pt/Vsm before next tile
    }

    // epilogue: write O/l to g_O[b][e][n]
    float linv[8];
    #pragma unroll
    for (int ii = 0; ii < 8; ii++) linv[ii] = 1.0f / lrow[ty*8 + ii];

    size_t base_n = (size_t)i0 + ty*8;
    #pragma unroll
    for (int k2 = 0; k2 < 4; k2++){
        float lo[8], hi[8];
        #pragma unroll
        for (int ii = 0; ii < 8; ii++) upk2(acc[ii][k2], lo[ii], hi[ii]);
        int e_base = (k2 >> 1)*128 + 4*tx + (k2 & 1)*2;
        #pragma unroll
        for (int h = 0; h < 2; h++){
            int e = e_base + h;
            size_t idx = (size_t)b*CH*NSP + (size_t)e*NSP + base_n;
            float vals[8];
            #pragma unroll
            for (int ii = 0; ii < 8; ii++)
                vals[ii] = (h ? hi[ii] : lo[ii]) * linv[ii];
            float4 o0 = make_float4(vals[0], vals[1], vals[2], vals[3]);
            float4 o1 = make_float4(vals[4], vals[5], vals[6], vals[7]);
            *(float4*)&Og[idx]     = o0;
            *(float4*)&Og[idx + 4] = o1;
        }
    }
}

// ---------------- epilogue: out = x + (gamma/sigma_v) * O -------------------
__global__ void epilogue_kernel(const float* __restrict__ x,
                                const float* __restrict__ gamma,
                                float* __restrict__ out){
    size_t i = ((size_t)blockIdx.x * 256 + threadIdx.x) * 4;
    float s = gamma[0] / g_sigma[2];
    float4 xv = *(const float4*)&x[i];
    float4 ov = *(const float4*)&g_O[i];
    float4 r = make_float4(xv.x + s*ov.x, xv.y + s*ov.y,
                           xv.z + s*ov.z, xv.w + s*ov.w);
    *(float4*)&out[i] = r;
}

// ---------------- launch ----------------------------------------------------
extern "C" void kernel_launch(void* const* d_in, const int* in_sizes, int n_in,
                              void* d_out, int out_size){
    (void)in_sizes; (void)n_in; (void)out_size;
    const float* x     = (const float*)d_in[0];
    const float* wq    = (const float*)d_in[1];
    const float* wk    = (const float*)d_in[2];
    const float* wv    = (const float*)d_in[3];
    const float* gamma = (const float*)d_in[4];
    float* out = (float*)d_out;

    cudaFuncSetAttribute(flash_kernel,
                         cudaFuncAttributeMaxDynamicSharedMemorySize, FLASH_SMEM);

    float* Og;
    cudaGetSymbolAddress((void**)&Og, g_O);

    // ours #1..#3, flash = ours #4  (profiled index 6 with harness offset 2)
    init_kernel<<<1, 32>>>();
    sigma_qk_kernel<<<2, 1024>>>(wq, wk);
    proj_all_kernel<<<dim3(NSP/64, BATCH, 6), 256>>>(x, wq, wk, wv);
    flash_kernel<<<dim3(NSP/64, BATCH), 256, FLASH_SMEM>>>(Og);

    // sigma_v chain (independent of flash): 5 squarings -> G^32 in g_GB
    gram_v_kernel<<<dim3(8, 8), 1024>>>(wv);
    sq_v_kernel<<<dim3(8, 8), 1024>>>(0, 1, 0);
    sq_v_kernel<<<dim3(8, 8), 1024>>>(1, 2, 1);
    sq_v_kernel<<<dim3(8, 8), 1024>>>(2, 1, 2);
    sq_v_kernel<<<dim3(8, 8), 1024>>>(1, 2, 3);
    sq_v_kernel<<<dim3(8, 8), 1024>>>(2, 1, 4);
    power_v_kernel<<<1, 1024>>>();

    epilogue_kernel<<<(BATCH*CH*NSP)/1024, 256>>>(x, gamma, out);
}

// round 14
// speedup vs baseline: 3.5218x; 1.6756x over previous
#include <cuda_runtime.h>
#include <math.h>
#include <stdint.h>

#define BATCH 4
#define CH    256
#define NSP   4096
#define DQK   32

// ---------------- scratch (__device__ globals: no runtime allocation) -------
__device__ __align__(256) float g_Q[BATCH*DQK*NSP];   // [b][d][n] fp32
__device__ __align__(256) float g_K[BATCH*DQK*NSP];   // [b][d][n] fp32
__device__ __align__(256) float g_V[BATCH*CH*NSP];    // [b][e][n] tf32-rounded
__device__ __align__(256) float g_O[BATCH*NSP*CH];    // [b][n][e] (pre-scale)
__device__ __align__(256) float g_G0[CH*CH];
__device__ __align__(256) float g_GA[CH*CH];
__device__ __align__(256) float g_GB[CH*CH];
__device__ float g_tr[16];
__device__ float g_sigma[4];   // [0]=sigma_q [1]=sigma_k [2]=sigma_v

// ---------------- packed f32x2 + tf32 helpers (Blackwell) -------------------
__device__ __forceinline__ unsigned long long pk2(float lo, float hi){
    unsigned long long r;
    asm("mov.b64 %0, {%1, %2};" : "=l"(r) : "f"(lo), "f"(hi));
    return r;
}
__device__ __forceinline__ unsigned long long ffma2(unsigned long long a,
                                                    unsigned long long b,
                                                    unsigned long long c){
    unsigned long long d;
    asm("fma.rn.f32x2 %0, %1, %2, %3;" : "=l"(d) : "l"(a), "l"(b), "l"(c));
    return d;
}
__device__ __forceinline__ unsigned long long fmul2(unsigned long long a,
                                                    unsigned long long b){
    unsigned long long d;
    asm("mul.rn.f32x2 %0, %1, %2;" : "=l"(d) : "l"(a), "l"(b));
    return d;
}
__device__ __forceinline__ float tf32r(float x){
    uint32_t u;
    asm("cvt.rna.tf32.f32 %0, %1;" : "=r"(u) : "f"(x));
    return __uint_as_float(u);
}
__device__ __forceinline__ uint32_t tf32u(float x){
    uint32_t u;
    asm("cvt.rna.tf32.f32 %0, %1;" : "=r"(u) : "f"(x));
    return u;
}
// D = A(16x8,row) * B(8x8,col) + D,  tf32 inputs, fp32 accum
__device__ __forceinline__ void mma_tf32(float* c, const uint32_t* a,
                                         uint32_t b0, uint32_t b1){
    asm volatile(
        "mma.sync.aligned.m16n8k8.row.col.f32.tf32.tf32.f32 "
        "{%0,%1,%2,%3}, {%4,%5,%6,%7}, {%8,%9}, {%0,%1,%2,%3};\n"
        : "+f"(c[0]), "+f"(c[1]), "+f"(c[2]), "+f"(c[3])
        : "r"(a[0]), "r"(a[1]), "r"(a[2]), "r"(a[3]), "r"(b0), "r"(b1));
}

// ---------------- cp.async helpers ------------------------------------------
__device__ __forceinline__ void cpa16(const float* dst, const float* src){
    uint32_t d = (uint32_t)__cvta_generic_to_shared(dst);
    asm volatile("cp.async.cg.shared.global [%0], [%1], 16;"
                 :: "r"(d), "l"(src) : "memory");
}
#define CP_COMMIT() asm volatile("cp.async.commit_group;" ::: "memory")
#define CP_WAIT(n)  asm volatile("cp.async.wait_group %0;" :: "n"(n) : "memory")

// ---------------- init ------------------------------------------------------
__global__ void init_kernel(){
    if (threadIdx.x < 16) g_tr[threadIdx.x] = 0.0f;
}

// ---------------- sigma for wq / wk (32x256) --------------------------------
__global__ void sigma_qk_kernel(const float* __restrict__ wq,
                                const float* __restrict__ wk){
    const float* W = (blockIdx.x == 0) ? wq : wk;
    __shared__ float Ws[32][257];
    __shared__ float Ao[32][33];
    __shared__ float Aa[32][33];
    __shared__ float Ab[32][33];
    __shared__ float vsh[32];
    __shared__ float tinv;
    int tid = threadIdx.x;

    for (int m = 0; m < 8; m++){
        int lin = m*1024 + tid;
        Ws[lin >> 8][lin & 255] = W[lin];
    }
    __syncthreads();

    int i = tid >> 5, j = tid & 31;
    float a = 0.f;
    #pragma unroll 8
    for (int c = 0; c < 256; c++) a += Ws[i][c] * Ws[j][c];
    Ao[i][j] = a;
    Aa[i][j] = a;
    __syncthreads();

    for (int s = 0; s < 5; s++){
        float (*cur)[33] = (s & 1) ? Ab : Aa;
        float (*nxt)[33] = (s & 1) ? Aa : Ab;
        if (tid == 0){
            float t = 0.f;
            for (int k2 = 0; k2 < 32; k2++) t += cur[k2][k2];
            tinv = 1.0f / t;
        }
        __syncthreads();
        float acc = 0.f;
        #pragma unroll
        for (int k2 = 0; k2 < 32; k2++) acc += cur[i][k2] * cur[j][k2];
        float ti = tinv;
        nxt[i][j] = acc * ti * ti;
        __syncthreads();
    }

    if (tid < 32){
        vsh[tid] = 1.0f + 0.05f * (float)tid;
        __syncwarp();
        for (int it = 0; it < 40; it++){
            float w = 0.f;
            #pragma unroll
            for (int k2 = 0; k2 < 32; k2++) w += Ab[tid][k2] * vsh[k2];
            float ss = w * w;
            #pragma unroll
            for (int off = 16; off; off >>= 1) ss += __shfl_xor_sync(0xffffffffu, ss, off);
            float sc = rsqrtf(ss);
            __syncwarp();
            vsh[tid] = w * sc;
            __syncwarp();
        }
        float w = 0.f;
        #pragma unroll
        for (int k2 = 0; k2 < 32; k2++) w += Ao[tid][k2] * vsh[k2];
        float num = vsh[tid] * w, den = vsh[tid] * vsh[tid];
        #pragma unroll
        for (int off = 16; off; off >>= 1){
            num += __shfl_xor_sync(0xffffffffu, num, off);
            den += __shfl_xor_sync(0xffffffffu, den, off);
        }
        if (tid == 0) g_sigma[blockIdx.x] = sqrtf(num / den);
    }
}

// ---------------- Gram of wv: G0 = wv wv^T (256x256) ------------------------
__global__ void gram_v_kernel(const float* __restrict__ wv){
    __shared__ float as[32][33], bs[32][33];
    int tid = threadIdx.x;
    int i0 = blockIdx.y * 32, j0 = blockIdx.x * 32;
    int li = tid >> 5, lj = tid & 31;
    float acc = 0.f;
    for (int c0 = 0; c0 < 256; c0 += 32){
        as[li][lj] = wv[(i0 + li)*256 + c0 + lj];
        bs[li][lj] = wv[(j0 + li)*256 + c0 + lj];
        __syncthreads();
        #pragma unroll
        for (int cc = 0; cc < 32; cc++) acc += as[li][cc] * bs[lj][cc];
        __syncthreads();
    }
    g_G0[(i0 + li)*256 + j0 + lj] = acc;
    if (i0 + li == j0 + lj) atomicAdd(&g_tr[0], acc);
}

// ---------------- one trace-normalized squaring of a 256x256 PSD matrix -----
__device__ __forceinline__ float* gbuf(int s){
    return (s == 0) ? g_G0 : ((s == 1) ? g_GA : g_GB);
}
__global__ void sq_v_kernel(int ssel, int dsel, int step){
    const float* src = gbuf(ssel);
    float* dst = gbuf(dsel);
    __shared__ float as[32][33], bs[32][33];
    int tid = threadIdx.x;
    int i0 = blockIdx.y * 32, j0 = blockIdx.x * 32;
    int li = tid >> 5, lj = tid & 31;
    float inv = 1.0f / g_tr[step];
    float acc = 0.f;
    for (int k0 = 0; k0 < 256; k0 += 32){
        as[li][lj] = src[(i0 + li)*256 + k0 + lj];
        bs[li][lj] = src[(j0 + li)*256 + k0 + lj];
        __syncthreads();
        #pragma unroll
        for (int kk = 0; kk < 32; kk++) acc += as[li][kk] * bs[lj][kk];
        __syncthreads();
    }
    acc = acc * inv * inv;
    dst[(i0 + li)*256 + j0 + lj] = acc;
    if (i0 + li == j0 + lj) atomicAdd(&g_tr[step + 1], acc);
}

// ---------------- power + Rayleigh for sigma_v ------------------------------
__global__ void power_v_kernel(){
    __shared__ float vsh[256], vnew[256];
    __shared__ float rss[8], rnum[8], rden[8];
    __shared__ float nscale;
    int tid = threadIdx.x;                // 1024 threads
    int lane = tid & 31, wrp = tid >> 5;
    if (tid < 256) vsh[tid] = 1.0f + 0.013f * (float)tid;
    __syncthreads();

    for (int it = 0; it < 9; it++){
        const float* Mat = (it < 8) ? g_GB : g_G0;
        float part[8] = {0,0,0,0,0,0,0,0};
        #pragma unroll
        for (int m = 0; m < 8; m++){
            int k2 = lane + 32*m;
            float vk = vsh[k2];
            #pragma unroll
            for (int i = 0; i < 8; i++)
                part[i] += Mat[(wrp*8 + i)*256 + k2] * vk;
        }
        #pragma unroll
        for (int i = 0; i < 8; i++){
            float r = part[i];
            #pragma unroll
            for (int off = 16; off; off >>= 1) r += __shfl_down_sync(0xffffffffu, r, off);
            if (lane == 0) vnew[wrp*8 + i] = r;
        }
        __syncthreads();
        if (it < 8){
            if (tid < 256){
                float s2 = vnew[tid] * vnew[tid];
                #pragma unroll
                for (int off = 16; off; off >>= 1) s2 += __shfl_down_sync(0xffffffffu, s2, off);
                if ((tid & 31) == 0) rss[tid >> 5] = s2;
            }
            __syncthreads();
            if (tid == 0){
                float s2 = 0.f;
                for (int u = 0; u < 8; u++) s2 += rss[u];
                nscale = rsqrtf(s2);
            }
            __syncthreads();
            if (tid < 256) vsh[tid] = vnew[tid] * nscale;
            __syncthreads();
        } else {
            if (tid < 256){
                float nv = vsh[tid] * vnew[tid];
                float dv = vsh[tid] * vsh[tid];
                #pragma unroll
                for (int off = 16; off; off >>= 1){
                    nv += __shfl_down_sync(0xffffffffu, nv, off);
                    dv += __shfl_down_sync(0xffffffffu, dv, off);
                }
                if ((tid & 31) == 0){ rnum[tid >> 5] = nv; rden[tid >> 5] = dv; }
            }
            __syncthreads();
            if (tid == 0){
                float n = 0.f, d2 = 0.f;
                for (int u = 0; u < 8; u++){ n += rnum[u]; d2 += rden[u]; }
                g_sigma[2] = sqrtf(n / d2);
            }
        }
    }
}

// ---------------- merged projections ----------------------------------------
// z = 0: Q -> g_Q[b][d][n] fp32   z = 1: K -> g_K[b][d][n] fp32
// z = 2..5: V -> g_V[b][e][n] tf32-rounded, e0 = (z-2)*64
__global__ void proj_all_kernel(const float* __restrict__ x,
                                const float* __restrict__ wq,
                                const float* __restrict__ wk,
                                const float* __restrict__ wv){
    int z = blockIdx.z;
    int b = blockIdx.y, n0 = blockIdx.x * 64;
    int tid = threadIdx.x;
    const float* xb = x + (size_t)b * CH * NSP;

    if (z < 2){
        const float* W = (z == 0) ? wq : wk;
        float* dst = ((z == 0) ? g_Q : g_K) + (size_t)b*DQK*NSP;
        __shared__ float ws[32][33], xs[32][65];
        int n = tid & 63, dg = tid >> 6;
        float acc[8] = {0,0,0,0,0,0,0,0};
        for (int c0 = 0; c0 < 256; c0 += 32){
            #pragma unroll
            for (int m = 0; m < 4; m++){
                int lin = m*256 + tid;
                ws[lin >> 5][lin & 31] = W[(lin >> 5)*256 + c0 + (lin & 31)];
            }
            #pragma unroll
            for (int m = 0; m < 8; m++){
                int lin = m*256 + tid;
                int c = lin >> 6, nn = lin & 63;
                xs[c][nn] = xb[(c0 + c)*NSP + n0 + nn];
            }
            __syncthreads();
            #pragma unroll
            for (int cc = 0; cc < 32; cc++){
                float xv = xs[cc][n];
                #pragma unroll
                for (int i = 0; i < 8; i++)
                    acc[i] += ws[dg*8 + i][cc] * xv;
            }
            __syncthreads();
        }
        #pragma unroll
        for (int i = 0; i < 8; i++)
            dst[(size_t)(dg*8 + i)*NSP + n0 + n] = acc[i];
    } else {
        int e0 = (z - 2) * 64;
        __shared__ float ws[64][33], xs[32][65];
        int ex = tid & 15, ny = tid >> 4;
        float acc[4][4] = {};
        for (int c0 = 0; c0 < 256; c0 += 32){
            #pragma unroll
            for (int m = 0; m < 8; m++){
                int lin = m*256 + tid;
                ws[lin >> 5][lin & 31] = wv[(e0 + (lin >> 5))*256 + c0 + (lin & 31)];
            }
            #pragma unroll
            for (int m = 0; m < 8; m++){
                int lin = m*256 + tid;
                int c = lin >> 6, nn = lin & 63;
                xs[c][nn] = xb[(c0 + c)*NSP + n0 + nn];
            }
            __syncthreads();
            #pragma unroll
            for (int cc = 0; cc < 32; cc++){
                float er[4], xr[4];
                #pragma unroll
                for (int jc = 0; jc < 4; jc++) er[jc] = ws[ex*4 + jc][cc];
                #pragma unroll
                for (int i = 0; i < 4; i++) xr[i] = xs[cc][ny*4 + i];
                #pragma unroll
                for (int i = 0; i < 4; i++)
                    #pragma unroll
                    for (int jc = 0; jc < 4; jc++)
                        acc[i][jc] += xr[i] * er[jc];
            }
            __syncthreads();
        }
        // store transposed [e][n], rounded to tf32
        #pragma unroll
        for (int jc = 0; jc < 4; jc++){
            float4 o = make_float4(tf32r(acc[0][jc]), tf32r(acc[1][jc]),
                                   tf32r(acc[2][jc]), tf32r(acc[3][jc]));
            *(float4*)&g_V[(size_t)b*CH*NSP + (size_t)(e0 + ex*4 + jc)*NSP + n0 + ny*4] = o;
        }
    }
}

// ---------------- flash attention (tf32 mma PV; writes O/l to g_O[b][n][e]) -
// Dynamic smem (floats):
//   Qs  @ 0      [32 d][68 q]   (2176)
//   Ks  @ 2176   [2][32 d][64 k](4096)
//   Ps  @ 6272   [64 q][68 k]   (4352)  P row-major (tf32 after softmax)
//   Vsm @ 10624  [256 e][68 k]  (17408) V^T tile (tf32)
//   mrow@ 28032, lrow@ 28096, arow@ 28160 -> 28224 floats = 112896 B
#define FLASH_SMEM 112896

__global__ void __launch_bounds__(256, 2)
flash_kernel(float* __restrict__ Og){
    extern __shared__ float sm[];
    float* Qs   = sm;
    float* Ks   = sm + 2176;
    float* Ps   = sm + 6272;
    float* Vsm  = sm + 10624;
    float* mrow = sm + 28032;
    float* lrow = sm + 28096;
    float* arow = sm + 28160;

    int tid  = threadIdx.x;
    int b = blockIdx.y, i0 = blockIdx.x * 64;
    int w    = tid >> 5, lane = tid & 31;
    int gid  = lane >> 2, tig = lane & 3;    // mma fragment coords
    int rid  = tid >> 4, cid = tid & 15;     // S-phase: rid=query grp, cid=key grp
    int ew   = w * 32;                       // this warp's e-slice

    const float* Qg = g_Q + (size_t)b*DQK*NSP;   // [d][n]
    const float* Kg = g_K + (size_t)b*DQK*NSP;   // [d][n]
    const float* Vg = g_V + (size_t)b*CH*NSP;    // [e][n] tf32

    float lscale = 1.0f / (g_sigma[0] * g_sigma[1] * sqrtf((float)DQK));

    // stage Q (plain loads)
    #pragma unroll
    for (int m = 0; m < 2; m++){
        int f = m*256 + tid;
        int d = f >> 4, u = f & 15;
        *(float4*)(Qs + d*68 + u*4) = *(const float4*)(Qg + (size_t)d*NSP + i0 + u*4);
    }
    if (tid < 64){ mrow[tid] = -INFINITY; lrow[tid] = 0.f; }

    float c[4][4][4];   // [mt][nt][frag]
    #pragma unroll
    for (int mt = 0; mt < 4; mt++)
        #pragma unroll
        for (int nt = 0; nt < 4; nt++)
            #pragma unroll
            for (int r = 0; r < 4; r++) c[mt][nt][r] = 0.f;

    // prefetch K tile 0
    #pragma unroll
    for (int m = 0; m < 2; m++){
        int f = m*256 + tid;
        int d = f >> 4, u = f & 15;
        cpa16(Ks + d*64 + u*4, Kg + (size_t)d*NSP + u*4);
    }
    CP_COMMIT();

    for (int jt = 0; jt < 64; jt++){
        int kb = jt & 1;
        int j0 = jt * 64;

        // stage V^T tile: 4 commit groups of 64 e-rows each
        #pragma unroll
        for (int g4 = 0; g4 < 4; g4++){
            #pragma unroll
            for (int i = 0; i < 4; i++){
                int f = i*256 + tid;
                int e = g4*64 + (f >> 4), u = f & 15;
                cpa16(Vsm + e*68 + u*4, Vg + (size_t)e*NSP + j0 + u*4);
            }
            CP_COMMIT();
        }

        CP_WAIT(4);          // K(jt) done
        __syncthreads();     // [1] Ks visible

        // S = Q K^T * lscale -> Ps[q][k] (f32x2 packed over keys; exact fp32)
        {
            const float* Kb = Ks + kb*2048;
            unsigned long long s2[4][2] = {{0ull,0ull},{0ull,0ull},
                                           {0ull,0ull},{0ull,0ull}};
            #pragma unroll
            for (int d = 0; d < 32; d++){
                ulonglong2 kp = *(const ulonglong2*)(Kb + d*64 + cid*4);
                #pragma unroll
                for (int i = 0; i < 4; i++){
                    float qv = Qs[d*68 + rid*4 + i];
                    unsigned long long q2 = pk2(qv, qv);
                    s2[i][0] = ffma2(kp.x, q2, s2[i][0]);
                    s2[i][1] = ffma2(kp.y, q2, s2[i][1]);
                }
            }
            unsigned long long ls2 = pk2(lscale, lscale);
            #pragma unroll
            for (int i = 0; i < 4; i++)
                #pragma unroll
                for (int j = 0; j < 2; j++){
                    unsigned long long v = fmul2(s2[i][j], ls2);
                    *(unsigned long long*)(Ps + (rid*4 + i)*68 + cid*4 + 2*j) = v;
                }
        }

        // prefetch next K tile
        {
            int nj = ((jt + 1) & 63) * 64;
            #pragma unroll
            for (int m = 0; m < 2; m++){
                int f = m*256 + tid;
                int d = f >> 4, u = f & 15;
                cpa16(Ks + (kb ^ 1)*2048 + d*64 + u*4,
                      Kg + (size_t)d*NSP + nj + u*4);
            }
            CP_COMMIT();
        }
        __syncwarp();        // S -> softmax is warp-local (rows 8w..8w+7)

        // streaming softmax on rows r = tid>>2 (warp-local); writeback as tf32
        {
            int r = tid >> 2, g = tid & 3;
            float* pr = Ps + r*68 + g*16;
            float4 pv[4];
            #pragma unroll
            for (int c4 = 0; c4 < 4; c4++) pv[c4] = *(const float4*)(pr + c4*4);
            float mx = -INFINITY;
            #pragma unroll
            for (int c4 = 0; c4 < 4; c4++)
                mx = fmaxf(mx, fmaxf(fmaxf(pv[c4].x, pv[c4].y),
                                     fmaxf(pv[c4].z, pv[c4].w)));
            mx = fmaxf(mx, __shfl_xor_sync(0xffffffffu, mx, 1));
            mx = fmaxf(mx, __shfl_xor_sync(0xffffffffu, mx, 2));
            float mold = mrow[r];
            float mnew = fmaxf(mold, mx);
            float sum = 0.f;
            #pragma unroll
            for (int c4 = 0; c4 < 4; c4++){
                float e0 = __expf(pv[c4].x - mnew);
                float e1 = __expf(pv[c4].y - mnew);
                float e2 = __expf(pv[c4].z - mnew);
                float e3 = __expf(pv[c4].w - mnew);
                sum += e0 + e1 + e2 + e3;
                uint4 uu = make_uint4(tf32u(e0), tf32u(e1), tf32u(e2), tf32u(e3));
                *(uint4*)(pr + c4*4) = uu;
            }
            sum += __shfl_xor_sync(0xffffffffu, sum, 1);
            sum += __shfl_xor_sync(0xffffffffu, sum, 2);
            if (g == 0){
                float al = __expf(mold - mnew);
                lrow[r] = lrow[r] * al + sum;
                mrow[r] = mnew;
                arow[r] = al;
            }
        }

        CP_WAIT(1);          // all 4 V groups done (K-next may pend)
        __syncthreads();     // [2] softmax + V visible everywhere

        // rescale accumulator (skip when all alphas == 1, warp-vote)
        {
            float ala[4], alb[4];
            bool mine = true;
            #pragma unroll
            for (int mt = 0; mt < 4; mt++){
                ala[mt] = arow[16*mt + gid];
                alb[mt] = arow[16*mt + gid + 8];
                mine = mine && (ala[mt] == 1.0f) && (alb[mt] == 1.0f);
            }
            if (!__all_sync(0xffffffffu, mine)){
                #pragma unroll
                for (int mt = 0; mt < 4; mt++)
                    #pragma unroll
                    for (int nt = 0; nt < 4; nt++){
                        c[mt][nt][0] *= ala[mt];
                        c[mt][nt][1] *= ala[mt];
                        c[mt][nt][2] *= alb[mt];
                        c[mt][nt][3] *= alb[mt];
                    }
            }
        }

        // PV: tf32 mma, 8 k-steps x 4 m-tiles x 4 n-tiles
        {
            const uint32_t* Pu = (const uint32_t*)Ps;
            const uint32_t* Vu = (const uint32_t*)Vsm;
            #pragma unroll
            for (int ks = 0; ks < 8; ks++){
                int kk = ks*8 + tig;
                uint32_t a[4][4];
                #pragma unroll
                for (int mt = 0; mt < 4; mt++){
                    int ra = (16*mt + gid)*68 + kk;
                    a[mt][0] = Pu[ra];
                    a[mt][1] = Pu[ra + 8*68];
                    a[mt][2] = Pu[ra + 4];
                    a[mt][3] = Pu[ra + 8*68 + 4];
                }
                #pragma unroll
                for (int nt = 0; nt < 4; nt++){
                    int eb = (ew + 8*nt + gid)*68 + kk;
                    uint32_t b0 = Vu[eb];
                    uint32_t b1 = Vu[eb + 4];
                    #pragma unroll
                    for (int mt = 0; mt < 4; mt++)
                        mma_tf32(c[mt][nt], a[mt], b0, b1);
                }
            }
        }
        __syncthreads();     // [3] Ps/Vsm free for next tile
    }

    // epilogue: O/l -> g_O[b][n][e]
    float lia[4], lib[4];
    #pragma unroll
    for (int mt = 0; mt < 4; mt++){
        lia[mt] = 1.0f / lrow[16*mt + gid];
        lib[mt] = 1.0f / lrow[16*mt + gid + 8];
    }
    float* Ob = Og + (size_t)b*NSP*CH;
    #pragma unroll
    for (int mt = 0; mt < 4; mt++){
        int q = i0 + 16*mt + gid;
        #pragma unroll
        for (int nt = 0; nt < 4; nt++){
            int e = ew + 8*nt + tig*2;
            float2 v0 = make_float2(c[mt][nt][0]*lia[mt], c[mt][nt][1]*lia[mt]);
            float2 v1 = make_float2(c[mt][nt][2]*lib[mt], c[mt][nt][3]*lib[mt]);
            *(float2*)&Ob[(size_t)q*CH + e]       = v0;
            *(float2*)&Ob[(size_t)(q + 8)*CH + e] = v1;
        }
    }
}

// ---------------- epilogue: out[b][e][n] = x + (gamma/sigma_v) * O^T --------
__global__ void epilogue_kernel(const float* __restrict__ x,
                                const float* __restrict__ gamma,
                                float* __restrict__ out){
    __shared__ float t[32][33];
    int b = blockIdx.z;
    int n0 = blockIdx.x * 32, e0 = blockIdx.y * 32;
    int tx = threadIdx.x, ty = threadIdx.y;   // 32 x 8
    float s = gamma[0] / g_sigma[2];
    const float* Ob = g_O + (size_t)b*NSP*CH;
    #pragma unroll
    for (int i = 0; i < 4; i++)
        t[ty + 8*i][tx] = Ob[(size_t)(n0 + ty + 8*i)*CH + e0 + tx];
    __syncthreads();
    #pragma unroll
    for (int i = 0; i < 4; i++){
        int e = e0 + ty + 8*i;
        size_t idx = (size_t)b*CH*NSP + (size_t)e*NSP + n0 + tx;
        out[idx] = x[idx] + s * t[tx][ty + 8*i];
    }
}

// ---------------- launch ----------------------------------------------------
extern "C" void kernel_launch(void* const* d_in, const int* in_sizes, int n_in,
                              void* d_out, int out_size){
    (void)in_sizes; (void)n_in; (void)out_size;
    const float* x     = (const float*)d_in[0];
    const float* wq    = (const float*)d_in[1];
    const float* wk    = (const float*)d_in[2];
    const float* wv    = (const float*)d_in[3];
    const float* gamma = (const float*)d_in[4];
    float* out = (float*)d_out;

    cudaFuncSetAttribute(flash_kernel,
                         cudaFuncAttributeMaxDynamicSharedMemorySize, FLASH_SMEM);

    float* Og;
    cudaGetSymbolAddress((void**)&Og, g_O);

    // ours #1..#3, flash = ours #4 (ncu profiles it with harness offset)
    init_kernel<<<1, 32>>>();
    sigma_qk_kernel<<<2, 1024>>>(wq, wk);
    proj_all_kernel<<<dim3(NSP/64, BATCH, 6), 256>>>(x, wq, wk, wv);
    flash_kernel<<<dim3(NSP/64, BATCH), 256, FLASH_SMEM>>>(Og);

    // sigma_v chain (independent of flash): 5 squarings -> G^32 in g_GB
    gram_v_kernel<<<dim3(8, 8), 1024>>>(wv);
    sq_v_kernel<<<dim3(8, 8), 1024>>>(0, 1, 0);
    sq_v_kernel<<<dim3(8, 8), 1024>>>(1, 2, 1);
    sq_v_kernel<<<dim3(8, 8), 1024>>>(2, 1, 2);
    sq_v_kernel<<<dim3(8, 8), 1024>>>(1, 2, 3);
    sq_v_kernel<<<dim3(8, 8), 1024>>>(2, 1, 4);
    power_v_kernel<<<1, 1024>>>();

    epilogue_kernel<<<dim3(NSP/32, CH/32, BATCH), dim3(32, 8)>>>(x, gamma, out);
}

// round 15
// speedup vs baseline: 4.2236x; 1.1993x over previous
#include <cuda_runtime.h>
#include <math.h>
#include <stdint.h>

#define BATCH 4
#define CH    256
#define NSP   4096
#define DQK   32

// ---------------- scratch (__device__ globals: no runtime allocation) -------
__device__ __align__(256) float g_Qhi[BATCH*NSP*DQK];  // [b][n][d] tf32(hi)
__device__ __align__(256) float g_Qlo[BATCH*NSP*DQK];  // [b][n][d] tf32(lo)
__device__ __align__(256) float g_Khi[BATCH*NSP*DQK];  // [b][n][d] tf32(hi)
__device__ __align__(256) float g_Klo[BATCH*NSP*DQK];  // [b][n][d] tf32(lo)
__device__ __align__(256) unsigned short g_Vb[BATCH*CH*NSP];  // [b][e][n] bf16
__device__ __align__(256) float g_O[BATCH*NSP*CH];     // [b][n][e] (pre-scale)
__device__ __align__(256) float g_G0[CH*CH];
__device__ __align__(256) float g_GA[CH*CH];
__device__ __align__(256) float g_GB[CH*CH];
__device__ float g_tr[16];
__device__ float g_sigma[4];   // [0]=sigma_q [1]=sigma_k [2]=sigma_v

// ---------------- helpers ----------------------------------------------------
__device__ __forceinline__ float tf32r(float x){
    uint32_t u;
    asm("cvt.rna.tf32.f32 %0, %1;" : "=r"(u) : "f"(x));
    return __uint_as_float(u);
}
// pack {lo(addr even), hi(addr odd)} into bf16x2 (first src -> upper half)
__device__ __forceinline__ uint32_t pkbf16(float lo, float hi){
    uint32_t u;
    asm("cvt.rn.bf16x2.f32 %0, %1, %2;" : "=r"(u) : "f"(hi), "f"(lo));
    return u;
}
// D += A(16x8,row,tf32) * B(8x8,col,tf32)
__device__ __forceinline__ void mma_tf32(float* c, const uint32_t* a,
                                         uint32_t b0, uint32_t b1){
    asm volatile(
        "mma.sync.aligned.m16n8k8.row.col.f32.tf32.tf32.f32 "
        "{%0,%1,%2,%3}, {%4,%5,%6,%7}, {%8,%9}, {%0,%1,%2,%3};\n"
        : "+f"(c[0]), "+f"(c[1]), "+f"(c[2]), "+f"(c[3])
        : "r"(a[0]), "r"(a[1]), "r"(a[2]), "r"(a[3]), "r"(b0), "r"(b1));
}
// D += A(16x16,row,bf16) * B(16x8,col,bf16)
__device__ __forceinline__ void mma_bf16(float* c, const uint32_t* a,
                                         uint32_t b0, uint32_t b1){
    asm volatile(
        "mma.sync.aligned.m16n8k16.row.col.f32.bf16.bf16.f32 "
        "{%0,%1,%2,%3}, {%4,%5,%6,%7}, {%8,%9}, {%0,%1,%2,%3};\n"
        : "+f"(c[0]), "+f"(c[1]), "+f"(c[2]), "+f"(c[3])
        : "r"(a[0]), "r"(a[1]), "r"(a[2]), "r"(a[3]), "r"(b0), "r"(b1));
}

// ---------------- cp.async helpers ------------------------------------------
__device__ __forceinline__ void cpa16(const void* dst, const void* src){
    uint32_t d = (uint32_t)__cvta_generic_to_shared(dst);
    asm volatile("cp.async.cg.shared.global [%0], [%1], 16;"
                 :: "r"(d), "l"(src) : "memory");
}
#define CP_COMMIT() asm volatile("cp.async.commit_group;" ::: "memory")
#define CP_WAIT(n)  asm volatile("cp.async.wait_group %0;" :: "n"(n) : "memory")

// ---------------- init ------------------------------------------------------
__global__ void init_kernel(){
    if (threadIdx.x < 16) g_tr[threadIdx.x] = 0.0f;
}

// ---------------- sigma for wq / wk (32x256) --------------------------------
__global__ void sigma_qk_kernel(const float* __restrict__ wq,
                                const float* __restrict__ wk){
    const float* W = (blockIdx.x == 0) ? wq : wk;
    __shared__ float Ws[32][257];
    __shared__ float Ao[32][33];
    __shared__ float Aa[32][33];
    __shared__ float Ab[32][33];
    __shared__ float vsh[32];
    __shared__ float tinv;
    int tid = threadIdx.x;

    for (int m = 0; m < 8; m++){
        int lin = m*1024 + tid;
        Ws[lin >> 8][lin & 255] = W[lin];
    }
    __syncthreads();

    int i = tid >> 5, j = tid & 31;
    float a = 0.f;
    #pragma unroll 8
    for (int c = 0; c < 256; c++) a += Ws[i][c] * Ws[j][c];
    Ao[i][j] = a;
    Aa[i][j] = a;
    __syncthreads();

    for (int s = 0; s < 5; s++){
        float (*cur)[33] = (s & 1) ? Ab : Aa;
        float (*nxt)[33] = (s & 1) ? Aa : Ab;
        if (tid == 0){
            float t = 0.f;
            for (int k2 = 0; k2 < 32; k2++) t += cur[k2][k2];
            tinv = 1.0f / t;
        }
        __syncthreads();
        float acc = 0.f;
        #pragma unroll
        for (int k2 = 0; k2 < 32; k2++) acc += cur[i][k2] * cur[j][k2];
        float ti = tinv;
        nxt[i][j] = acc * ti * ti;
        __syncthreads();
    }

    if (tid < 32){
        vsh[tid] = 1.0f + 0.05f * (float)tid;
        __syncwarp();
        for (int it = 0; it < 40; it++){
            float w = 0.f;
            #pragma unroll
            for (int k2 = 0; k2 < 32; k2++) w += Ab[tid][k2] * vsh[k2];
            float ss = w * w;
            #pragma unroll
            for (int off = 16; off; off >>= 1) ss += __shfl_xor_sync(0xffffffffu, ss, off);
            float sc = rsqrtf(ss);
            __syncwarp();
            vsh[tid] = w * sc;
            __syncwarp();
        }
        float w = 0.f;
        #pragma unroll
        for (int k2 = 0; k2 < 32; k2++) w += Ao[tid][k2] * vsh[k2];
        float num = vsh[tid] * w, den = vsh[tid] * vsh[tid];
        #pragma unroll
        for (int off = 16; off; off >>= 1){
            num += __shfl_xor_sync(0xffffffffu, num, off);
            den += __shfl_xor_sync(0xffffffffu, den, off);
        }
        if (tid == 0) g_sigma[blockIdx.x] = sqrtf(num / den);
    }
}

// ---------------- Gram of wv: G0 = wv wv^T (256x256) ------------------------
__global__ void gram_v_kernel(const float* __restrict__ wv){
    __shared__ float as[32][33], bs[32][33];
    int tid = threadIdx.x;
    int i0 = blockIdx.y * 32, j0 = blockIdx.x * 32;
    int li = tid >> 5, lj = tid & 31;
    float acc = 0.f;
    for (int c0 = 0; c0 < 256; c0 += 32){
        as[li][lj] = wv[(i0 + li)*256 + c0 + lj];
        bs[li][lj] = wv[(j0 + li)*256 + c0 + lj];
        __syncthreads();
        #pragma unroll
        for (int cc = 0; cc < 32; cc++) acc += as[li][cc] * bs[lj][cc];
        __syncthreads();
    }
    g_G0[(i0 + li)*256 + j0 + lj] = acc;
    if (i0 + li == j0 + lj) atomicAdd(&g_tr[0], acc);
}

// ---------------- one trace-normalized squaring of a 256x256 PSD matrix -----
__device__ __forceinline__ float* gbuf(int s){
    return (s == 0) ? g_G0 : ((s == 1) ? g_GA : g_GB);
}
__global__ void sq_v_kernel(int ssel, int dsel, int step){
    const float* src = gbuf(ssel);
    float* dst = gbuf(dsel);
    __shared__ float as[32][33], bs[32][33];
    int tid = threadIdx.x;
    int i0 = blockIdx.y * 32, j0 = blockIdx.x * 32;
    int li = tid >> 5, lj = tid & 31;
    float inv = 1.0f / g_tr[step];
    float acc = 0.f;
    for (int k0 = 0; k0 < 256; k0 += 32){
        as[li][lj] = src[(i0 + li)*256 + k0 + lj];
        bs[li][lj] = src[(j0 + li)*256 + k0 + lj];
        __syncthreads();
        #pragma unroll
        for (int kk = 0; kk < 32; kk++) acc += as[li][kk] * bs[lj][kk];
        __syncthreads();
    }
    acc = acc * inv * inv;
    dst[(i0 + li)*256 + j0 + lj] = acc;
    if (i0 + li == j0 + lj) atomicAdd(&g_tr[step + 1], acc);
}

// ---------------- power + Rayleigh for sigma_v ------------------------------
__global__ void power_v_kernel(){
    __shared__ float vsh[256], vnew[256];
    __shared__ float rss[8], rnum[8], rden[8];
    __shared__ float nscale;
    int tid = threadIdx.x;                // 1024 threads
    int lane = tid & 31, wrp = tid >> 5;
    if (tid < 256) vsh[tid] = 1.0f + 0.013f * (float)tid;
    __syncthreads();

    for (int it = 0; it < 9; it++){
        const float* Mat = (it < 8) ? g_GB : g_G0;
        float part[8] = {0,0,0,0,0,0,0,0};
        #pragma unroll
        for (int m = 0; m < 8; m++){
            int k2 = lane + 32*m;
            float vk = vsh[k2];
            #pragma unroll
            for (int i = 0; i < 8; i++)
                part[i] += Mat[(wrp*8 + i)*256 + k2] * vk;
        }
        #pragma unroll
        for (int i = 0; i < 8; i++){
            float r = part[i];
            #pragma unroll
            for (int off = 16; off; off >>= 1) r += __shfl_down_sync(0xffffffffu, r, off);
            if (lane == 0) vnew[wrp*8 + i] = r;
        }
        __syncthreads();
        if (it < 8){
            if (tid < 256){
                float s2 = vnew[tid] * vnew[tid];
                #pragma unroll
                for (int off = 16; off; off >>= 1) s2 += __shfl_down_sync(0xffffffffu, s2, off);
                if ((tid & 31) == 0) rss[tid >> 5] = s2;
            }
            __syncthreads();
            if (tid == 0){
                float s2 = 0.f;
                for (int u = 0; u < 8; u++) s2 += rss[u];
                nscale = rsqrtf(s2);
            }
            __syncthreads();
            if (tid < 256) vsh[tid] = vnew[tid] * nscale;
            __syncthreads();
        } else {
            if (tid < 256){
                float nv = vsh[tid] * vnew[tid];
                float dv = vsh[tid] * vsh[tid];
                #pragma unroll
                for (int off = 16; off; off >>= 1){
                    nv += __shfl_down_sync(0xffffffffu, nv, off);
                    dv += __shfl_down_sync(0xffffffffu, dv, off);
                }
                if ((tid & 31) == 0){ rnum[tid >> 5] = nv; rden[tid >> 5] = dv; }
            }
            __syncthreads();
            if (tid == 0){
                float n = 0.f, d2 = 0.f;
                for (int u = 0; u < 8; u++){ n += rnum[u]; d2 += rden[u]; }
                g_sigma[2] = sqrtf(n / d2);
            }
        }
    }
}

// ---------------- merged projections ----------------------------------------
// z = 0: Q -> g_Qhi/g_Qlo [b][n][d]   z = 1: K -> g_Khi/g_Klo [b][n][d]
// z = 2..5: V -> g_Vb [b][e][n] bf16, e0 = (z-2)*64
__global__ void proj_all_kernel(const float* __restrict__ x,
                                const float* __restrict__ wq,
                                const float* __restrict__ wk,
                                const float* __restrict__ wv){
    int z = blockIdx.z;
    int b = blockIdx.y, n0 = blockIdx.x * 64;
    int tid = threadIdx.x;
    const float* xb = x + (size_t)b * CH * NSP;

    if (z < 2){
        const float* W = (z == 0) ? wq : wk;
        float* dhi = ((z == 0) ? g_Qhi : g_Khi) + (size_t)b*NSP*DQK;
        float* dlo = ((z == 0) ? g_Qlo : g_Klo) + (size_t)b*NSP*DQK;
        __shared__ float ws[32][33], xs[32][65];
        int d = tid & 31, rg = tid >> 5;
        float acc[8] = {0,0,0,0,0,0,0,0};
        for (int c0 = 0; c0 < 256; c0 += 32){
            #pragma unroll
            for (int m = 0; m < 4; m++){
                int lin = m*256 + tid;
                ws[lin >> 5][lin & 31] = W[(lin >> 5)*256 + c0 + (lin & 31)];
            }
            #pragma unroll
            for (int m = 0; m < 8; m++){
                int lin = m*256 + tid;
                int c = lin >> 6, nn = lin & 63;
                xs[c][nn] = xb[(c0 + c)*NSP + n0 + nn];
            }
            __syncthreads();
            #pragma unroll
            for (int cc = 0; cc < 32; cc++){
                float wv_ = ws[d][cc];
                #pragma unroll
                for (int i = 0; i < 8; i++) acc[i] += wv_ * xs[cc][rg*8 + i];
            }
            __syncthreads();
        }
        #pragma unroll
        for (int i = 0; i < 8; i++){
            float hi = tf32r(acc[i]);
            float lo = tf32r(acc[i] - hi);
            size_t idx = (size_t)(n0 + rg*8 + i)*DQK + d;
            dhi[idx] = hi;
            dlo[idx] = lo;
        }
    } else {
        int e0 = (z - 2) * 64;
        __shared__ float ws[64][33], xs[32][65];
        int ex = tid & 15, ny = tid >> 4;
        float acc[4][4] = {};
        for (int c0 = 0; c0 < 256; c0 += 32){
            #pragma unroll
            for (int m = 0; m < 8; m++){
                int lin = m*256 + tid;
                ws[lin >> 5][lin & 31] = wv[(e0 + (lin >> 5))*256 + c0 + (lin & 31)];
            }
            #pragma unroll
            for (int m = 0; m < 8; m++){
                int lin = m*256 + tid;
                int c = lin >> 6, nn = lin & 63;
                xs[c][nn] = xb[(c0 + c)*NSP + n0 + nn];
            }
            __syncthreads();
            #pragma unroll
            for (int cc = 0; cc < 32; cc++){
                float er[4], xr[4];
                #pragma unroll
                for (int jc = 0; jc < 4; jc++) er[jc] = ws[ex*4 + jc][cc];
                #pragma unroll
                for (int i = 0; i < 4; i++) xr[i] = xs[cc][ny*4 + i];
                #pragma unroll
                for (int i = 0; i < 4; i++)
                    #pragma unroll
                    for (int jc = 0; jc < 4; jc++)
                        acc[i][jc] += xr[i] * er[jc];
            }
            __syncthreads();
        }
        // store bf16 [e][n]
        #pragma unroll
        for (int jc = 0; jc < 4; jc++){
            uint32_t u0 = pkbf16(acc[0][jc], acc[1][jc]);
            uint32_t u1 = pkbf16(acc[2][jc], acc[3][jc]);
            size_t h = (size_t)b*CH*NSP + (size_t)(e0 + ex*4 + jc)*NSP + n0 + ny*4;
            *(uint2*)&g_Vb[h] = make_uint2(u0, u1);
        }
    }
}

// ---------------- flash attention (tensor-core S + PV) ----------------------
// smem (float offsets):
//   Qhi @0 [64][36], Qlo @2304 [64][36]
//   Khi @4608 [64][36], Klo @6912 [64][36]
//   Ps  @9216  [64 q][68 k] fp32 raw S
//   Pb  @13568 [64 q][36 u32] bf16x2 P (k-pairs)
//   Vsm @15872 [256 e][36 u32] bf16x2 V (k-pairs)
//   mrow @25088, lrow @25152, arow @25216 -> 25280 floats = 101120 B
#define FLASH_SMEM 101120

__global__ void __launch_bounds__(256, 2)
flash_kernel(float* __restrict__ Og){
    extern __shared__ float sm[];
    float*     Qhi = sm;
    float*     Qlo = sm + 2304;
    float*     Khi = sm + 4608;
    float*     Klo = sm + 6912;
    float*     Ps  = sm + 9216;
    uint32_t*  Pbu = (uint32_t*)(sm + 13568);
    uint32_t*  Vu  = (uint32_t*)(sm + 15872);
    float*     mrow = sm + 25088;
    float*     lrow = sm + 25152;
    float*     arow = sm + 25216;

    int tid  = threadIdx.x;
    int b = blockIdx.y, i0 = blockIdx.x * 64;
    int w    = tid >> 5, lane = tid & 31;
    int gid  = lane >> 2, tig = lane & 3;
    int ew   = w * 32;                       // PV e-slice per warp

    const float* gQh = g_Qhi + (size_t)b*NSP*DQK;
    const float* gQl = g_Qlo + (size_t)b*NSP*DQK;
    const float* gKh = g_Khi + (size_t)b*NSP*DQK;
    const float* gKl = g_Klo + (size_t)b*NSP*DQK;
    const unsigned short* gV = g_Vb + (size_t)b*CH*NSP;

    float lscale = 1.0f / (g_sigma[0] * g_sigma[1] * sqrtf((float)DQK));

    // stage Q hi/lo [64][36]
    #pragma unroll
    for (int m = 0; m < 2; m++){
        int f = m*256 + tid;
        int r = f >> 3, q8 = f & 7;
        *(float4*)(Qhi + r*36 + q8*4) = *(const float4*)(gQh + (size_t)(i0 + r)*DQK + q8*4);
        *(float4*)(Qlo + r*36 + q8*4) = *(const float4*)(gQl + (size_t)(i0 + r)*DQK + q8*4);
    }
    if (tid < 64){ mrow[tid] = -INFINITY; lrow[tid] = 0.f; }

    float c[4][4][4];   // [mt][nt][frag]
    #pragma unroll
    for (int mt = 0; mt < 4; mt++)
        #pragma unroll
        for (int nt = 0; nt < 4; nt++)
            #pragma unroll
            for (int r = 0; r < 4; r++) c[mt][nt][r] = 0.f;
    __syncthreads();     // Q staged (plain stores) before first S

    for (int jt = 0; jt < 64; jt++){
        int j0 = jt * 64;

        // group 1: K tile hi+lo [64][36]
        #pragma unroll
        for (int m = 0; m < 2; m++){
            int f = m*256 + tid;
            int r = f >> 3, q8 = f & 7;
            cpa16(Khi + r*36 + q8*4, gKh + (size_t)(j0 + r)*DQK + q8*4);
            cpa16(Klo + r*36 + q8*4, gKl + (size_t)(j0 + r)*DQK + q8*4);
        }
        CP_COMMIT();
        // groups 2-5: V tile bf16 [256 e][64 k] -> rows of 72 halves
        #pragma unroll
        for (int g4 = 0; g4 < 4; g4++){
            #pragma unroll
            for (int i = 0; i < 2; i++){
                int cix = i*256 + tid;
                int e = g4*64 + (cix >> 3), u = cix & 7;
                cpa16((unsigned short*)Vu + e*72 + u*8,
                      gV + (size_t)e*NSP + j0 + u*8);
            }
            CP_COMMIT();
        }

        CP_WAIT(4);          // K ready
        __syncthreads();     // [B1]

        // ---- S = Q K^T (3-term tf32 mma) -> Ps[q][8w..8w+7] raw ----
        {
            const uint32_t* Qh = (const uint32_t*)Qhi;
            const uint32_t* Ql = (const uint32_t*)Qlo;
            const uint32_t* Kh = (const uint32_t*)Khi;
            const uint32_t* Kl = (const uint32_t*)Klo;
            float cs[4][4];
            #pragma unroll
            for (int mt = 0; mt < 4; mt++)
                #pragma unroll
                for (int r = 0; r < 4; r++) cs[mt][r] = 0.f;

            #pragma unroll
            for (int kd = 0; kd < 4; kd++){
                int krow = (8*w + gid)*36 + kd*8 + tig;
                uint32_t bh0 = Kh[krow],     bh1 = Kh[krow + 4];
                uint32_t bl0 = Kl[krow],     bl1 = Kl[krow + 4];
                #pragma unroll
                for (int mt = 0; mt < 4; mt++){
                    int r0 = (16*mt + gid)*36 + kd*8 + tig;
                    int r1 = (16*mt + gid + 8)*36 + kd*8 + tig;
                    uint32_t ah[4] = {Qh[r0], Qh[r1], Qh[r0 + 4], Qh[r1 + 4]};
                    uint32_t al[4] = {Ql[r0], Ql[r1], Ql[r0 + 4], Ql[r1 + 4]};
                    mma_tf32(cs[mt], ah, bh0, bh1);
                    mma_tf32(cs[mt], al, bh0, bh1);
                    mma_tf32(cs[mt], ah, bl0, bl1);
                }
            }
            #pragma unroll
            for (int mt = 0; mt < 4; mt++){
                int col = 8*w + 2*tig;
                *(float2*)(Ps + (16*mt + gid)*68 + col)     =
                    make_float2(cs[mt][0], cs[mt][1]);
                *(float2*)(Ps + (16*mt + gid + 8)*68 + col) =
                    make_float2(cs[mt][2], cs[mt][3]);
            }
        }
        __syncthreads();     // [B2] all S columns written

        // ---- streaming softmax (scale by lscale here); write bf16 P ----
        {
            int r = tid >> 2, g = tid & 3;
            const float* pr = Ps + r*68 + g*16;
            float v[16];
            #pragma unroll
            for (int c4 = 0; c4 < 4; c4++){
                float4 p4 = *(const float4*)(pr + c4*4);
                v[c4*4+0] = p4.x * lscale; v[c4*4+1] = p4.y * lscale;
                v[c4*4+2] = p4.z * lscale; v[c4*4+3] = p4.w * lscale;
            }
            float mx = -INFINITY;
            #pragma unroll
            for (int q2 = 0; q2 < 16; q2++) mx = fmaxf(mx, v[q2]);
            mx = fmaxf(mx, __shfl_xor_sync(0xffffffffu, mx, 1));
            mx = fmaxf(mx, __shfl_xor_sync(0xffffffffu, mx, 2));
            float mold = mrow[r];
            float mnew = fmaxf(mold, mx);
            float sum = 0.f;
            #pragma unroll
            for (int c4 = 0; c4 < 4; c4++){
                float e0 = __expf(v[c4*4+0] - mnew);
                float e1 = __expf(v[c4*4+1] - mnew);
                float e2 = __expf(v[c4*4+2] - mnew);
                float e3 = __expf(v[c4*4+3] - mnew);
                sum += e0 + e1 + e2 + e3;
                Pbu[r*36 + g*8 + c4*2]     = pkbf16(e0, e1);
                Pbu[r*36 + g*8 + c4*2 + 1] = pkbf16(e2, e3);
            }
            sum += __shfl_xor_sync(0xffffffffu, sum, 1);
            sum += __shfl_xor_sync(0xffffffffu, sum, 2);
            if (g == 0){
                float al = __expf(mold - mnew);
                lrow[r] = lrow[r] * al + sum;
                mrow[r] = mnew;
                arow[r] = al;
            }
        }

        CP_WAIT(0);          // all V groups done
        __syncthreads();     // [B3]

        // rescale accumulator (skip when all alphas == 1, warp-vote)
        {
            float ala[4], alb[4];
            bool mine = true;
            #pragma unroll
            for (int mt = 0; mt < 4; mt++){
                ala[mt] = arow[16*mt + gid];
                alb[mt] = arow[16*mt + gid + 8];
                mine = mine && (ala[mt] == 1.0f) && (alb[mt] == 1.0f);
            }
            if (!__all_sync(0xffffffffu, mine)){
                #pragma unroll
                for (int mt = 0; mt < 4; mt++)
                    #pragma unroll
                    for (int nt = 0; nt < 4; nt++){
                        c[mt][nt][0] *= ala[mt];
                        c[mt][nt][1] *= ala[mt];
                        c[mt][nt][2] *= alb[mt];
                        c[mt][nt][3] *= alb[mt];
                    }
            }
        }

        // ---- PV: bf16 m16n8k16, 4 k-steps x 4 m x 4 n ----
        #pragma unroll
        for (int ks = 0; ks < 4; ks++){
            uint32_t a[4][4];
            #pragma unroll
            for (int mt = 0; mt < 4; mt++){
                int r0 = (16*mt + gid)*36 + ks*8 + tig;
                int r1 = (16*mt + gid + 8)*36 + ks*8 + tig;
                a[mt][0] = Pbu[r0];
                a[mt][1] = Pbu[r1];
                a[mt][2] = Pbu[r0 + 4];
                a[mt][3] = Pbu[r1 + 4];
            }
            #pragma unroll
            for (int nt = 0; nt < 4; nt++){
                int eb = (ew + 8*nt + gid)*36 + ks*8 + tig;
                uint32_t b0 = Vu[eb];
                uint32_t b1 = Vu[eb + 4];
                #pragma unroll
                for (int mt = 0; mt < 4; mt++)
                    mma_bf16(c[mt][nt], a[mt], b0, b1);
            }
        }
        __syncthreads();     // [B4] Ps/Pb/Vsm/K free for next tile
    }

    // epilogue: O/l -> g_O[b][n][e]
    float lia[4], lib[4];
    #pragma unroll
    for (int mt = 0; mt < 4; mt++){
        lia[mt] = 1.0f / lrow[16*mt + gid];
        lib[mt] = 1.0f / lrow[16*mt + gid + 8];
    }
    float* Ob = Og + (size_t)b*NSP*CH;
    #pragma unroll
    for (int mt = 0; mt < 4; mt++){
        int q = i0 + 16*mt + gid;
        #pragma unroll
        for (int nt = 0; nt < 4; nt++){
            int e = ew + 8*nt + tig*2;
            float2 v0 = make_float2(c[mt][nt][0]*lia[mt], c[mt][nt][1]*lia[mt]);
            float2 v1 = make_float2(c[mt][nt][2]*lib[mt], c[mt][nt][3]*lib[mt]);
            *(float2*)&Ob[(size_t)q*CH + e]       = v0;
            *(float2*)&Ob[(size_t)(q + 8)*CH + e] = v1;
        }
    }
}

// ---------------- epilogue: out[b][e][n] = x + (gamma/sigma_v) * O^T --------
__global__ void epilogue_kernel(const float* __restrict__ x,
                                const float* __restrict__ gamma,
                                float* __restrict__ out){
    __shared__ float t[32][33];
    int b = blockIdx.z;
    int n0 = blockIdx.x * 32, e0 = blockIdx.y * 32;
    int tx = threadIdx.x, ty = threadIdx.y;   // 32 x 8
    float s = gamma[0] / g_sigma[2];
    const float* Ob = g_O + (size_t)b*NSP*CH;
    #pragma unroll
    for (int i = 0; i < 4; i++)
        t[ty + 8*i][tx] = Ob[(size_t)(n0 + ty + 8*i)*CH + e0 + tx];
    __syncthreads();
    #pragma unroll
    for (int i = 0; i < 4; i++){
        int e = e0 + ty + 8*i;
        size_t idx = (size_t)b*CH*NSP + (size_t)e*NSP + n0 + tx;
        out[idx] = x[idx] + s * t[tx][ty + 8*i];
    }
}

// ---------------- launch ----------------------------------------------------
extern "C" void kernel_launch(void* const* d_in, const int* in_sizes, int n_in,
                              void* d_out, int out_size){
    (void)in_sizes; (void)n_in; (void)out_size;
    const float* x     = (const float*)d_in[0];
    const float* wq    = (const float*)d_in[1];
    const float* wk    = (const float*)d_in[2];
    const float* wv    = (const float*)d_in[3];
    const float* gamma = (const float*)d_in[4];
    float* out = (float*)d_out;

    cudaFuncSetAttribute(flash_kernel,
                         cudaFuncAttributeMaxDynamicSharedMemorySize, FLASH_SMEM);

    float* Og;
    cudaGetSymbolAddress((void**)&Og, g_O);

    // ours #1..#3, flash = ours #4 (ncu profiles it with harness offset)
    init_kernel<<<1, 32>>>();
    sigma_qk_kernel<<<2, 1024>>>(wq, wk);
    proj_all_kernel<<<dim3(NSP/64, BATCH, 6), 256>>>(x, wq, wk, wv);
    flash_kernel<<<dim3(NSP/64, BATCH), 256, FLASH_SMEM>>>(Og);

    // sigma_v chain (independent of flash): 5 squarings -> G^32 in g_GB
    gram_v_kernel<<<dim3(8, 8), 1024>>>(wv);
    sq_v_kernel<<<dim3(8, 8), 1024>>>(0, 1, 0);
    sq_v_kernel<<<dim3(8, 8), 1024>>>(1, 2, 1);
    sq_v_kernel<<<dim3(8, 8), 1024>>>(2, 1, 2);
    sq_v_kernel<<<dim3(8, 8), 1024>>>(1, 2, 3);
    sq_v_kernel<<<dim3(8, 8), 1024>>>(2, 1, 4);
    power_v_kernel<<<1, 1024>>>();

    epilogue_kernel<<<dim3(NSP/32, CH/32, BATCH), dim3(32, 8)>>>(x, gamma, out);
}